// round 2
// baseline (speedup 1.0000x reference)
#include <cuda_runtime.h>
#include <math.h>

#define Ldim 128
#define Bdim 128
#define Vdim 300
#define Hdim 256
#define NEx  5
#define NCh  10      // 5 experts x 2 directions
#define G4   1024    // 4*H
#define H2   512     // 2*H

// ---------------- device scratch (no allocations allowed) ----------------
__device__ float g_PROJ[(size_t)NCh * Ldim * Bdim * G4];   // [c][t][b][g]  (671 MB)
__device__ float g_HS[(size_t)NEx * Bdim * Ldim * H2];     // [e][b][l][2H] (168 MB)
__device__ float g_Hst[2][(size_t)NCh * Bdim * Hdim];      // double-buffered h state
__device__ float g_Cst[(size_t)NCh * Bdim * Hdim];         // c state (in-place)
__device__ float g_s[(size_t)NEx * Bdim * Ldim];           // attention logits
__device__ float g_OUT[(size_t)NEx * Bdim * H2];           // pooled outputs

__device__ __forceinline__ float sigf(float x) { return 1.0f / (1.0f + expf(-x)); }

// ---------------- init: zero recurrent state ----------------
__global__ void init_kernel() {
    int i = blockIdx.x * blockDim.x + threadIdx.x;
    int n = NCh * Bdim * Hdim;
    if (i < n) { g_Hst[0][i] = 0.0f; g_Cst[i] = 0.0f; }
}

// ---------------- input projection GEMM ----------------
// XG[m, n] = sum_v x[m, v] * wih[n, v]  (+bias), scattered into g_PROJ with
// time-reversal for backward chains. M=16384, N=10240, K=300.
// Tile 128x128x16, 256 threads, 8x8 per thread.
__global__ __launch_bounds__(256) void proj_kernel(
    const float* __restrict__ x,
    const float* __restrict__ wf, const float* __restrict__ wb,
    const float* __restrict__ bf, const float* __restrict__ bb)
{
    __shared__ float As[16][128];
    __shared__ float Bs[16][128];

    const int m0 = blockIdx.y * 128;
    const int n0 = blockIdx.x * 128;
    const int tid = threadIdx.x;
    const int tx = tid & 15, ty = tid >> 4;

    const int c = n0 >> 10;           // chain (constant per tile: 1024 % 128 == 0)
    const int e = c >> 1, d = c & 1;
    const float* wbase = (d ? wb : wf) + (size_t)e * G4 * Vdim;
    const int g0 = n0 & 1023;

    float acc[8][8];
#pragma unroll
    for (int r = 0; r < 8; r++)
#pragma unroll
        for (int j = 0; j < 8; j++) acc[r][j] = 0.0f;

    for (int k0 = 0; k0 < Vdim; k0 += 16) {
        // A tile: 128 rows x 16 k
        {
            int i = tid * 8;
            int mm = i >> 4, kk = i & 15;
            const float* xrow = x + (size_t)(m0 + mm) * Vdim + k0;
#pragma unroll
            for (int j = 0; j < 8; j++) {
                float v = (k0 + kk + j < Vdim) ? xrow[kk + j] : 0.0f;
                As[kk + j][mm] = v;
            }
        }
        // B tile: 128 weight rows x 16 k
        {
            int i = tid * 8;
            int nn = i >> 4, kk = i & 15;
            const float* wrow = wbase + (size_t)(g0 + nn) * Vdim + k0;
#pragma unroll
            for (int j = 0; j < 8; j++) {
                float v = (k0 + kk + j < Vdim) ? wrow[kk + j] : 0.0f;
                Bs[kk + j][nn] = v;
            }
        }
        __syncthreads();
#pragma unroll
        for (int k = 0; k < 16; k++) {
            float a[8], b[8];
#pragma unroll
            for (int r = 0; r < 8; r++) a[r] = As[k][ty * 8 + r];
#pragma unroll
            for (int j = 0; j < 8; j++) b[j] = Bs[k][tx * 8 + j];
#pragma unroll
            for (int r = 0; r < 8; r++)
#pragma unroll
                for (int j = 0; j < 8; j++) acc[r][j] += a[r] * b[j];
        }
        __syncthreads();
    }

    // epilogue: +bias, scatter with time reversal for backward chains
    const float* bias = (d ? bb : bf) + (size_t)e * G4;
    float bv[8];
#pragma unroll
    for (int j = 0; j < 8; j++) bv[j] = bias[g0 + tx * 8 + j];

    const int b_i = m0 >> 7;  // whole tile is inside one batch row (128-row tiles)
#pragma unroll
    for (int r = 0; r < 8; r++) {
        int l = ty * 8 + r;
        int t = d ? (Ldim - 1 - l) : l;
        float* dst = g_PROJ + (((size_t)c * Ldim + t) * Bdim + b_i) * G4 + g0 + tx * 8;
#pragma unroll
        for (int j = 0; j < 8; j++) dst[j] = acc[r][j] + bv[j];
    }
}

// ---------------- one LSTM time step (all 10 chains) ----------------
// Per CTA: chain c, 64 batch rows, 32 h-dims (=> 128 gate columns, all 4 gates).
// gates = PROJ[c][t] + Hprev @ Wslice^T ; pointwise update is register-local.
__global__ __launch_bounds__(128) void lstm_step_kernel(
    const float* __restrict__ whf, const float* __restrict__ whb, int t)
{
    __shared__ float As[32][64];
    __shared__ float Bs[32][128];

    const int c = blockIdx.z;
    const int b0 = blockIdx.y * 64;
    const int hd0 = blockIdx.x * 32;
    const int e = c >> 1, d = c & 1;
    const float* wbase = (d ? whb : whf) + (size_t)e * G4 * Hdim;
    const float* Hprev = g_Hst[t & 1] + (size_t)c * Bdim * Hdim;
    float* Hnext = g_Hst[(t & 1) ^ 1] + (size_t)c * Bdim * Hdim;

    const int tid = threadIdx.x;        // 128
    const int tx = tid & 15, ty = tid >> 4;  // ty 0..7 (8 rows each), tx 0..15 (2 hd each)

    // init accumulators from PROJ (bias already folded in)
    float acc[8][8];
    const float* projb = g_PROJ + (((size_t)c * Ldim + t) * Bdim + b0) * G4;
#pragma unroll
    for (int r = 0; r < 8; r++) {
        int b_l = ty * 8 + r;
#pragma unroll
        for (int gg = 0; gg < 4; gg++)
#pragma unroll
            for (int j = 0; j < 2; j++)
                acc[r][gg * 2 + j] = projb[(size_t)b_l * G4 + gg * Hdim + hd0 + tx * 2 + j];
    }

    for (int k0 = 0; k0 < Hdim; k0 += 32) {
        // A: 64 b-rows x 32 k
        {
            int i = tid * 16;
            int mm = i >> 5, kk = i & 31;
            const float* hp = Hprev + (size_t)(b0 + mm) * Hdim + k0 + kk;
#pragma unroll
            for (int j = 0; j < 16; j++) As[kk + j][mm] = hp[j];
        }
        // B: 128 gate-rows x 32 k (thread = one column, conflict-free stores)
        {
            int nn = tid;
            int gate = nn >> 5;
            int hd = hd0 + (nn & 31);
            const float* wr = wbase + (size_t)(gate * Hdim + hd) * Hdim + k0;
#pragma unroll
            for (int j = 0; j < 32; j++) Bs[j][nn] = wr[j];
        }
        __syncthreads();
#pragma unroll
        for (int k = 0; k < 32; k++) {
            float a[8], b[8];
#pragma unroll
            for (int r = 0; r < 8; r++) a[r] = As[k][ty * 8 + r];
#pragma unroll
            for (int gg = 0; gg < 4; gg++) {
                b[gg * 2 + 0] = Bs[k][gg * 32 + tx * 2 + 0];
                b[gg * 2 + 1] = Bs[k][gg * 32 + tx * 2 + 1];
            }
#pragma unroll
            for (int r = 0; r < 8; r++)
#pragma unroll
                for (int j = 0; j < 8; j++) acc[r][j] += a[r] * b[j];
        }
        __syncthreads();
    }

    // pointwise LSTM update (each thread owns all 4 gates of its h-dims)
    const int lo = d ? (Ldim - 1 - t) : t;
#pragma unroll
    for (int r = 0; r < 8; r++) {
        int bg = b0 + ty * 8 + r;
#pragma unroll
        for (int j = 0; j < 2; j++) {
            int hd = hd0 + tx * 2 + j;
            float iv = sigf(acc[r][0 * 2 + j]);
            float fv = sigf(acc[r][1 * 2 + j]);
            float gv = tanhf(acc[r][2 * 2 + j]);
            float ov = sigf(acc[r][3 * 2 + j]);
            size_t cidx = ((size_t)c * Bdim + bg) * Hdim + hd;
            float cn = fv * g_Cst[cidx] + iv * gv;
            g_Cst[cidx] = cn;
            float hn = ov * tanhf(cn);
            Hnext[(size_t)bg * Hdim + hd] = hn;
            g_HS[(((size_t)e * Bdim + bg) * Ldim + lo) * H2 + d * Hdim + hd] = hn;
        }
    }
}

// ---------------- attention logits ----------------
// s[e][m] = sum_o tanh(HS[e][m] . attW[e][o] + attb[e][o]) * attv[e][o]
// Per CTA: 128 rows, loops all 4 N-tiles internally (no atomics -> deterministic).
__global__ __launch_bounds__(256) void attn_kernel(
    const float* __restrict__ attW, const float* __restrict__ attb,
    const float* __restrict__ attv)
{
    __shared__ float As[16][128];
    __shared__ float Bs[16][128];
    __shared__ float red[128][17];

    const int e = blockIdx.y;
    const int m0 = blockIdx.x * 128;
    const float* Abase = g_HS + (size_t)e * Bdim * Ldim * H2;
    const float* Wbase = attW + (size_t)e * H2 * H2;
    const int tid = threadIdx.x;
    const int tx = tid & 15, ty = tid >> 4;

    float part[8];
#pragma unroll
    for (int r = 0; r < 8; r++) part[r] = 0.0f;

    for (int nc = 0; nc < 4; nc++) {
        const int n0 = nc * 128;
        float acc[8][8];
#pragma unroll
        for (int r = 0; r < 8; r++)
#pragma unroll
            for (int j = 0; j < 8; j++) acc[r][j] = 0.0f;

        for (int k0 = 0; k0 < H2; k0 += 16) {
            {
                int i = tid * 8;
                int mm = i >> 4, kk = i & 15;
                const float* arow = Abase + (size_t)(m0 + mm) * H2 + k0;
#pragma unroll
                for (int j = 0; j < 8; j++) As[kk + j][mm] = arow[kk + j];
            }
            {
                int i = tid * 8;
                int nn = i >> 4, kk = i & 15;
                const float* wrow = Wbase + (size_t)(n0 + nn) * H2 + k0;
#pragma unroll
                for (int j = 0; j < 8; j++) Bs[kk + j][nn] = wrow[kk + j];
            }
            __syncthreads();
#pragma unroll
            for (int k = 0; k < 16; k++) {
                float a[8], b[8];
#pragma unroll
                for (int r = 0; r < 8; r++) a[r] = As[k][ty * 8 + r];
#pragma unroll
                for (int j = 0; j < 8; j++) b[j] = Bs[k][tx * 8 + j];
#pragma unroll
                for (int r = 0; r < 8; r++)
#pragma unroll
                    for (int j = 0; j < 8; j++) acc[r][j] += a[r] * b[j];
            }
            __syncthreads();
        }
        // fused epilogue: tanh + dot with attv
#pragma unroll
        for (int j = 0; j < 8; j++) {
            int o = n0 + tx * 8 + j;
            float ab = attb[(size_t)e * H2 + o];
            float av = attv[(size_t)e * H2 + o];
#pragma unroll
            for (int r = 0; r < 8; r++)
                part[r] += tanhf(acc[r][j] + ab) * av;
        }
    }

#pragma unroll
    for (int r = 0; r < 8; r++) red[ty * 8 + r][tx] = part[r];
    __syncthreads();
    if (tid < 128) {
        float ssum = 0.0f;
#pragma unroll
        for (int q = 0; q < 16; q++) ssum += red[tid][q];
        g_s[(size_t)e * Bdim * Ldim + m0 + tid] = ssum;
    }
}

// ---------------- softmax over L + weighted pooling ----------------
__global__ __launch_bounds__(128) void softmax_pool_kernel()
{
    const int e = blockIdx.y, b = blockIdx.x;
    __shared__ float wts[Ldim];
    __shared__ float red[128];
    const int tid = threadIdx.x;   // 128 == L

    float v = g_s[((size_t)e * Bdim + b) * Ldim + tid];
    red[tid] = v; __syncthreads();
    for (int st = 64; st > 0; st >>= 1) {
        if (tid < st) red[tid] = fmaxf(red[tid], red[tid + st]);
        __syncthreads();
    }
    float mx = red[0]; __syncthreads();
    float ev = expf(v - mx);
    red[tid] = ev; __syncthreads();
    for (int st = 64; st > 0; st >>= 1) {
        if (tid < st) red[tid] += red[tid + st];
        __syncthreads();
    }
    float inv = 1.0f / red[0];
    wts[tid] = ev * inv;
    __syncthreads();

    const float* hrow = g_HS + ((size_t)e * Bdim + b) * Ldim * H2;
    float accv[4] = {0.f, 0.f, 0.f, 0.f};
    for (int l = 0; l < Ldim; l++) {
        float a = wts[l];
        const float* hp = hrow + (size_t)l * H2;
#pragma unroll
        for (int j = 0; j < 4; j++) accv[j] += a * hp[tid + j * 128];
    }
    float* op = g_OUT + ((size_t)e * Bdim + b) * H2;
#pragma unroll
    for (int j = 0; j < 4; j++) op[tid + j * 128] = accv[j];
}

// ---------------- output copy: general + specifics ----------------
__global__ void copy_out_kernel(float* __restrict__ out)
{
    int i = blockIdx.x * blockDim.x + threadIdx.x;
    if (i < NEx * Bdim * H2) out[256 + i] = g_OUT[i];
}

// ---------------- gather + final FC ----------------
__global__ __launch_bounds__(128) void final_kernel(
    const int* __restrict__ z, const float* __restrict__ fcW,
    const float* __restrict__ fcb, float* __restrict__ out)
{
    const int b = blockIdx.x;
    const int tid = threadIdx.x;   // 128
    const int zi = z[b];
    const float* sel = g_OUT + ((size_t)(1 + zi) * Bdim + b) * H2;
    const float* gen = g_OUT + (size_t)b * H2;
    __shared__ float red0[128], red1[128];
    float a0 = 0.f, a1 = 0.f;
    for (int dd = tid; dd < 1024; dd += 128) {
        float cv = (dd < 512) ? sel[dd] : gen[dd - 512];
        a0 += cv * fcW[dd];
        a1 += cv * fcW[1024 + dd];
    }
    red0[tid] = a0; red1[tid] = a1; __syncthreads();
    for (int st = 64; st > 0; st >>= 1) {
        if (tid < st) { red0[tid] += red0[tid + st]; red1[tid] += red1[tid + st]; }
        __syncthreads();
    }
    if (tid == 0) {
        out[b * 2 + 0] = red0[0] + fcb[0];
        out[b * 2 + 1] = red1[0] + fcb[1];
    }
}

// ---------------- launch ----------------
extern "C" void kernel_launch(void* const* d_in, const int* in_sizes, int n_in,
                              void* d_out, int out_size)
{
    (void)in_sizes; (void)n_in; (void)out_size;
    const float* x     = (const float*)d_in[0];
    const int*   z     = (const int*)  d_in[1];
    const float* wih_f = (const float*)d_in[2];
    const float* whh_f = (const float*)d_in[3];
    const float* b_f   = (const float*)d_in[4];
    const float* wih_b = (const float*)d_in[5];
    const float* whh_b = (const float*)d_in[6];
    const float* b_b   = (const float*)d_in[7];
    const float* attW  = (const float*)d_in[8];
    const float* attb  = (const float*)d_in[9];
    const float* attv  = (const float*)d_in[10];
    const float* fcW   = (const float*)d_in[11];
    const float* fcb   = (const float*)d_in[12];
    float* out = (float*)d_out;

    init_kernel<<<(NCh * Bdim * Hdim + 255) / 256, 256>>>();
    proj_kernel<<<dim3(80, 128), 256>>>(x, wih_f, wih_b, b_f, b_b);
    for (int t = 0; t < Ldim; t++)
        lstm_step_kernel<<<dim3(8, 2, 10), 128>>>(whh_f, whh_b, t);
    attn_kernel<<<dim3(128, 5), 256>>>(attW, attb, attv);
    softmax_pool_kernel<<<dim3(128, 5), 128>>>();
    copy_out_kernel<<<(NEx * Bdim * H2 + 255) / 256, 256>>>(out);
    final_kernel<<<128, 128>>>(z, fcW, fcb, out);
}

// round 3
// speedup vs baseline: 1.5681x; 1.5681x over previous
#include <cuda_runtime.h>
#include <math.h>

#define Ldim 128
#define Bdim 128
#define Vdim 300
#define Hdim 256
#define NEx  5
#define NCh  10      // 5 experts x 2 directions
#define G4   1024    // 4*H
#define H2   512     // 2*H

// ---------------- device scratch (no allocations allowed) ----------------
__device__ float g_PROJ[(size_t)NCh * Ldim * Bdim * G4];   // [c][t][b][g]
__device__ float g_HS[(size_t)NEx * Bdim * Ldim * H2];     // [e][b][l][2H]
__device__ float g_Hst[2][(size_t)NCh * Bdim * Hdim];      // double-buffered h state
__device__ float g_s[(size_t)NEx * Bdim * Ldim];           // attention logits
__device__ float g_OUT[(size_t)NEx * Bdim * H2];           // pooled outputs
__device__ unsigned int g_bar_arrive[NCh];                 // zero-init
__device__ unsigned int g_bar_gen[NCh];                    // monotonically increasing

// ---------------- helpers ----------------
__device__ __forceinline__ float sigf(float x) { return 1.0f / (1.0f + __expf(-x)); }
__device__ __forceinline__ float tanh_fast(float x) {
    float cx = fminf(fmaxf(x, -15.0f), 15.0f);
    float e = __expf(2.0f * cx);
    return (e - 1.0f) / (e + 1.0f);
}
__device__ __forceinline__ unsigned long long packf2(float lo, float hi) {
    unsigned long long r;
    asm("mov.b64 %0, {%1,%2};" : "=l"(r) : "f"(lo), "f"(hi));
    return r;
}
__device__ __forceinline__ float2 unpackf2(unsigned long long v) {
    float2 p;
    asm("mov.b64 {%0,%1}, %2;" : "=f"(p.x), "=f"(p.y) : "l"(v));
    return p;
}
__device__ __forceinline__ void fmaf2(unsigned long long& d, unsigned long long a, unsigned long long b) {
    asm("fma.rn.f32x2 %0, %1, %2, %0;" : "+l"(d) : "l"(a), "l"(b));
}

// ---------------- input projection GEMM (FFMA2) ----------------
// XG[m, n] = sum_v x[m, v] * wih[n, v]  (+bias), scattered into g_PROJ with
// time-reversal for backward chains. M=16384, N=10240, K=300.
__global__ __launch_bounds__(256) void proj_kernel(
    const float* __restrict__ x,
    const float* __restrict__ wf, const float* __restrict__ wb,
    const float* __restrict__ bf, const float* __restrict__ bb)
{
    __shared__ float As[16][128];
    __shared__ float Bs[16][128];

    const int m0 = blockIdx.y * 128;
    const int n0 = blockIdx.x * 128;
    const int tid = threadIdx.x;
    const int tx = tid & 15, ty = tid >> 4;

    const int c = n0 >> 10;
    const int e = c >> 1, d = c & 1;
    const float* wbase = (d ? wb : wf) + (size_t)e * G4 * Vdim;
    const int g0 = n0 & 1023;

    unsigned long long acc2[4][8];
#pragma unroll
    for (int i = 0; i < 4; i++)
#pragma unroll
        for (int j = 0; j < 8; j++) acc2[i][j] = 0ull;

    for (int k0 = 0; k0 < Vdim; k0 += 16) {
        {
            int i = tid * 8;
            int mm = i >> 4, kk = i & 15;
            const float* xrow = x + (size_t)(m0 + mm) * Vdim + k0;
#pragma unroll
            for (int j = 0; j < 8; j++) {
                float v = (k0 + kk + j < Vdim) ? xrow[kk + j] : 0.0f;
                As[kk + j][mm] = v;
            }
        }
        {
            int i = tid * 8;
            int nn = i >> 4, kk = i & 15;
            const float* wrow = wbase + (size_t)(g0 + nn) * Vdim + k0;
#pragma unroll
            for (int j = 0; j < 8; j++) {
                float v = (k0 + kk + j < Vdim) ? wrow[kk + j] : 0.0f;
                Bs[kk + j][nn] = v;
            }
        }
        __syncthreads();
#pragma unroll
        for (int k = 0; k < 16; k++) {
            unsigned long long a2[4], b2[8];
            const unsigned long long* arow = (const unsigned long long*)&As[k][ty * 8];
#pragma unroll
            for (int i = 0; i < 4; i++) a2[i] = arow[i];
#pragma unroll
            for (int j = 0; j < 8; j++) {
                float bw = Bs[k][tx * 8 + j];
                b2[j] = packf2(bw, bw);
            }
#pragma unroll
            for (int i = 0; i < 4; i++)
#pragma unroll
                for (int j = 0; j < 8; j++) fmaf2(acc2[i][j], a2[i], b2[j]);
        }
        __syncthreads();
    }

    const float* bias = (d ? bb : bf) + (size_t)e * G4;
    float bv[8];
#pragma unroll
    for (int j = 0; j < 8; j++) bv[j] = bias[g0 + tx * 8 + j];

    const int b_i = m0 >> 7;
#pragma unroll
    for (int i = 0; i < 4; i++) {
        int l0 = ty * 8 + 2 * i;
        int t_a = d ? (Ldim - 1 - l0) : l0;
        int t_b = d ? (Ldim - 1 - (l0 + 1)) : (l0 + 1);
        float* dstA = g_PROJ + (((size_t)c * Ldim + t_a) * Bdim + b_i) * G4 + g0 + tx * 8;
        float* dstB = g_PROJ + (((size_t)c * Ldim + t_b) * Bdim + b_i) * G4 + g0 + tx * 8;
#pragma unroll
        for (int j = 0; j < 8; j++) {
            float2 v = unpackf2(acc2[i][j]);
            dstA[j] = v.x + bv[j];
            dstB[j] = v.y + bv[j];
        }
    }
}

// ---------------- persistent LSTM recurrence ----------------
// Grid 160 = 10 chains x 16 hd-slices. Each CTA owns 16 h-dims (64 gate cols),
// caches its W_hh slice in SMEM for all 128 steps, keeps c-state in registers,
// and synchronizes its chain via a global sense-free generation barrier.
#define SMEM_LSTM ((256 * 64 + 2 * 32 * 132) * 4)   // 99328 bytes

__global__ __launch_bounds__(256, 2) void lstm_persist_kernel(
    const float* __restrict__ whf, const float* __restrict__ whb)
{
    extern __shared__ float sm[];
    float* Ws = sm;                      // [k=256][cl=64]
    float* Hs0 = sm + 256 * 64;          // [32][132]
    float* Hs1 = Hs0 + 32 * 132;

    const int bid = blockIdx.x;
    const int c = bid >> 4, p = bid & 15;
    const int hd0 = p * 16;
    const int e = c >> 1, d = c & 1;
    const float* wbase = (d ? whb : whf) + (size_t)e * G4 * Hdim;

    const int tid = threadIdx.x;
    const int tx = tid & 15, ty = tid >> 4;

    // ---- load W slice into SMEM once (cols: cl = g*16 + j -> row g*256+hd0+j) ----
    {
        int cl = tid & 63;
        int ks = (tid >> 6) * 64;
        int g = cl >> 4, j = cl & 15;
        const float4* wr = (const float4*)(wbase + (size_t)(g * 256 + hd0 + j) * Hdim + ks);
#pragma unroll
        for (int k4 = 0; k4 < 16; k4++) {
            float4 w = wr[k4];
            Ws[(ks + k4 * 4 + 0) * 64 + cl] = w.x;
            Ws[(ks + k4 * 4 + 1) * 64 + cl] = w.y;
            Ws[(ks + k4 * 4 + 2) * 64 + cl] = w.z;
            Ws[(ks + k4 * 4 + 3) * 64 + cl] = w.w;
        }
    }

    unsigned int bgen = 0;
    if (tid == 0) bgen = *(volatile unsigned int*)&g_bar_gen[c];
    __syncthreads();

    float cst[8];
#pragma unroll
    for (int i = 0; i < 8; i++) cst[i] = 0.0f;

    const int mrow = tid >> 1;     // 0..127 (batch) for tile loading
    const int kh = tid & 1;        // 0..1 (16-k half)
    const int hd = hd0 + tx;

    for (int t = 0; t < Ldim; t++) {
        // accumulators init from PROJ (bias folded in)
        unsigned long long acc2[4][4];
        const float* projb = g_PROJ + (((size_t)c * Ldim + t) * Bdim) * G4;
#pragma unroll
        for (int i = 0; i < 4; i++) {
            int b = ty * 8 + 2 * i;
            const float* q = projb + (size_t)b * G4 + hd0 + tx;
#pragma unroll
            for (int g = 0; g < 4; g++) {
                const float* qq = q + g * Hdim;
                acc2[i][g] = packf2(__ldcg(qq), __ldcg(qq + G4));
            }
        }

        if (t > 0) {
            const float* Hp = g_Hst[t & 1] + (size_t)c * Bdim * Hdim;
            // preload tile 0
            {
                const float4* src = (const float4*)(Hp + (size_t)mrow * Hdim + kh * 16);
                float4 f0 = __ldcg(src), f1 = __ldcg(src + 1), f2 = __ldcg(src + 2), f3 = __ldcg(src + 3);
                float* hb = Hs0;
                int kb = kh * 16;
                hb[(kb + 0) * 132 + mrow] = f0.x; hb[(kb + 1) * 132 + mrow] = f0.y;
                hb[(kb + 2) * 132 + mrow] = f0.z; hb[(kb + 3) * 132 + mrow] = f0.w;
                hb[(kb + 4) * 132 + mrow] = f1.x; hb[(kb + 5) * 132 + mrow] = f1.y;
                hb[(kb + 6) * 132 + mrow] = f1.z; hb[(kb + 7) * 132 + mrow] = f1.w;
                hb[(kb + 8) * 132 + mrow] = f2.x; hb[(kb + 9) * 132 + mrow] = f2.y;
                hb[(kb + 10) * 132 + mrow] = f2.z; hb[(kb + 11) * 132 + mrow] = f2.w;
                hb[(kb + 12) * 132 + mrow] = f3.x; hb[(kb + 13) * 132 + mrow] = f3.y;
                hb[(kb + 14) * 132 + mrow] = f3.z; hb[(kb + 15) * 132 + mrow] = f3.w;
            }
            __syncthreads();
            for (int kt = 0; kt < 8; kt++) {
                float4 f0, f1, f2, f3;
                if (kt < 7) {
                    const float4* src = (const float4*)(Hp + (size_t)mrow * Hdim + (kt + 1) * 32 + kh * 16);
                    f0 = __ldcg(src); f1 = __ldcg(src + 1); f2 = __ldcg(src + 2); f3 = __ldcg(src + 3);
                }
                const float* hb = (kt & 1) ? Hs1 : Hs0;
                const float* wk = Ws + kt * 32 * 64;
#pragma unroll 4
                for (int kk = 0; kk < 32; kk++) {
                    const float* hr = hb + kk * 132 + ty * 8;
                    unsigned long long a2[4];
#pragma unroll
                    for (int i = 0; i < 4; i++)
                        a2[i] = *(const unsigned long long*)(hr + 2 * i);
#pragma unroll
                    for (int g = 0; g < 4; g++) {
                        float bw = wk[kk * 64 + g * 16 + tx];
                        unsigned long long b2 = packf2(bw, bw);
#pragma unroll
                        for (int i = 0; i < 4; i++) fmaf2(acc2[i][g], a2[i], b2);
                    }
                }
                if (kt < 7) {
                    float* hb2 = (kt & 1) ? Hs0 : Hs1;
                    int kb = kh * 16;
                    hb2[(kb + 0) * 132 + mrow] = f0.x; hb2[(kb + 1) * 132 + mrow] = f0.y;
                    hb2[(kb + 2) * 132 + mrow] = f0.z; hb2[(kb + 3) * 132 + mrow] = f0.w;
                    hb2[(kb + 4) * 132 + mrow] = f1.x; hb2[(kb + 5) * 132 + mrow] = f1.y;
                    hb2[(kb + 6) * 132 + mrow] = f1.z; hb2[(kb + 7) * 132 + mrow] = f1.w;
                    hb2[(kb + 8) * 132 + mrow] = f2.x; hb2[(kb + 9) * 132 + mrow] = f2.y;
                    hb2[(kb + 10) * 132 + mrow] = f2.z; hb2[(kb + 11) * 132 + mrow] = f2.w;
                    hb2[(kb + 12) * 132 + mrow] = f3.x; hb2[(kb + 13) * 132 + mrow] = f3.y;
                    hb2[(kb + 14) * 132 + mrow] = f3.z; hb2[(kb + 15) * 132 + mrow] = f3.w;
                }
                __syncthreads();
            }
        }

        // pointwise LSTM update; write h to next buffer + g_HS
        float* Hn = g_Hst[(t & 1) ^ 1] + (size_t)c * Bdim * Hdim;
        const int lo = d ? (Ldim - 1 - t) : t;
#pragma unroll
        for (int i = 0; i < 4; i++) {
            float2 iv2 = unpackf2(acc2[i][0]);
            float2 fv2 = unpackf2(acc2[i][1]);
            float2 gv2 = unpackf2(acc2[i][2]);
            float2 ov2 = unpackf2(acc2[i][3]);
            int b = ty * 8 + 2 * i;
            {
                float cn = sigf(fv2.x) * cst[2 * i] + sigf(iv2.x) * tanh_fast(gv2.x);
                cst[2 * i] = cn;
                float hn = sigf(ov2.x) * tanh_fast(cn);
                Hn[(size_t)b * Hdim + hd] = hn;
                g_HS[(((size_t)e * Bdim + b) * Ldim + lo) * H2 + d * Hdim + hd] = hn;
            }
            {
                float cn = sigf(fv2.y) * cst[2 * i + 1] + sigf(iv2.y) * tanh_fast(gv2.y);
                cst[2 * i + 1] = cn;
                float hn = sigf(ov2.y) * tanh_fast(cn);
                Hn[(size_t)(b + 1) * Hdim + hd] = hn;
                g_HS[(((size_t)e * Bdim + (b + 1)) * Ldim + lo) * H2 + d * Hdim + hd] = hn;
            }
        }

        // chain barrier
        __threadfence();
        __syncthreads();
        if (tid == 0) {
            unsigned int a = atomicAdd(&g_bar_arrive[c], 1u);
            unsigned int target = bgen + (unsigned)t + 1u;
            if (a == 15u) {
                atomicExch(&g_bar_arrive[c], 0u);
                __threadfence();
                atomicAdd(&g_bar_gen[c], 1u);
            } else {
                while ((int)(*(volatile unsigned int*)&g_bar_gen[c] - target) < 0)
                    __nanosleep(64);
            }
            __threadfence();
        }
        __syncthreads();
    }
}

// ---------------- attention logits (FFMA2) ----------------
__global__ __launch_bounds__(256) void attn_kernel(
    const float* __restrict__ attW, const float* __restrict__ attb,
    const float* __restrict__ attv)
{
    __shared__ float As[16][128];
    __shared__ float Bs[16][128];
    __shared__ float red[128][17];

    const int e = blockIdx.y;
    const int m0 = blockIdx.x * 128;
    const float* Abase = g_HS + (size_t)e * Bdim * Ldim * H2;
    const float* Wbase = attW + (size_t)e * H2 * H2;
    const int tid = threadIdx.x;
    const int tx = tid & 15, ty = tid >> 4;

    float part[8];
#pragma unroll
    for (int r = 0; r < 8; r++) part[r] = 0.0f;

    for (int nc = 0; nc < 4; nc++) {
        const int n0 = nc * 128;
        unsigned long long acc2[4][8];
#pragma unroll
        for (int i = 0; i < 4; i++)
#pragma unroll
            for (int j = 0; j < 8; j++) acc2[i][j] = 0ull;

        for (int k0 = 0; k0 < H2; k0 += 16) {
            {
                int i = tid * 8;
                int mm = i >> 4, kk = i & 15;
                const float* arow = Abase + (size_t)(m0 + mm) * H2 + k0;
#pragma unroll
                for (int j = 0; j < 8; j++) As[kk + j][mm] = arow[kk + j];
            }
            {
                int i = tid * 8;
                int nn = i >> 4, kk = i & 15;
                const float* wrow = Wbase + (size_t)(n0 + nn) * H2 + k0;
#pragma unroll
                for (int j = 0; j < 8; j++) Bs[kk + j][nn] = wrow[kk + j];
            }
            __syncthreads();
#pragma unroll
            for (int k = 0; k < 16; k++) {
                unsigned long long a2[4], b2[8];
                const unsigned long long* arow = (const unsigned long long*)&As[k][ty * 8];
#pragma unroll
                for (int i = 0; i < 4; i++) a2[i] = arow[i];
#pragma unroll
                for (int j = 0; j < 8; j++) {
                    float bw = Bs[k][tx * 8 + j];
                    b2[j] = packf2(bw, bw);
                }
#pragma unroll
                for (int i = 0; i < 4; i++)
#pragma unroll
                    for (int j = 0; j < 8; j++) fmaf2(acc2[i][j], a2[i], b2[j]);
            }
            __syncthreads();
        }
#pragma unroll
        for (int j = 0; j < 8; j++) {
            int o = n0 + tx * 8 + j;
            float ab = attb[(size_t)e * H2 + o];
            float av = attv[(size_t)e * H2 + o];
#pragma unroll
            for (int i = 0; i < 4; i++) {
                float2 v = unpackf2(acc2[i][j]);
                part[2 * i] += tanh_fast(v.x + ab) * av;
                part[2 * i + 1] += tanh_fast(v.y + ab) * av;
            }
        }
    }

#pragma unroll
    for (int r = 0; r < 8; r++) red[ty * 8 + r][tx] = part[r];
    __syncthreads();
    if (tid < 128) {
        float ssum = 0.0f;
#pragma unroll
        for (int q = 0; q < 16; q++) ssum += red[tid][q];
        g_s[(size_t)e * Bdim * Ldim + m0 + tid] = ssum;
    }
}

// ---------------- softmax over L + weighted pooling ----------------
__global__ __launch_bounds__(128) void softmax_pool_kernel()
{
    const int e = blockIdx.y, b = blockIdx.x;
    __shared__ float wts[Ldim];
    __shared__ float red[128];
    const int tid = threadIdx.x;

    float v = g_s[((size_t)e * Bdim + b) * Ldim + tid];
    red[tid] = v; __syncthreads();
    for (int st = 64; st > 0; st >>= 1) {
        if (tid < st) red[tid] = fmaxf(red[tid], red[tid + st]);
        __syncthreads();
    }
    float mx = red[0]; __syncthreads();
    float ev = expf(v - mx);
    red[tid] = ev; __syncthreads();
    for (int st = 64; st > 0; st >>= 1) {
        if (tid < st) red[tid] += red[tid + st];
        __syncthreads();
    }
    float inv = 1.0f / red[0];
    wts[tid] = ev * inv;
    __syncthreads();

    const float* hrow = g_HS + ((size_t)e * Bdim + b) * Ldim * H2;
    float accv[4] = {0.f, 0.f, 0.f, 0.f};
    for (int l = 0; l < Ldim; l++) {
        float a = wts[l];
        const float* hp = hrow + (size_t)l * H2;
#pragma unroll
        for (int j = 0; j < 4; j++) accv[j] += a * hp[tid + j * 128];
    }
    float* op = g_OUT + ((size_t)e * Bdim + b) * H2;
#pragma unroll
    for (int j = 0; j < 4; j++) op[tid + j * 128] = accv[j];
}

// ---------------- output copy: general + specifics ----------------
__global__ void copy_out_kernel(float* __restrict__ out)
{
    int i = blockIdx.x * blockDim.x + threadIdx.x;
    if (i < NEx * Bdim * H2) out[256 + i] = g_OUT[i];
}

// ---------------- gather + final FC ----------------
__global__ __launch_bounds__(128) void final_kernel(
    const int* __restrict__ z, const float* __restrict__ fcW,
    const float* __restrict__ fcb, float* __restrict__ out)
{
    const int b = blockIdx.x;
    const int tid = threadIdx.x;
    const int zi = z[b];
    const float* sel = g_OUT + ((size_t)(1 + zi) * Bdim + b) * H2;
    const float* gen = g_OUT + (size_t)b * H2;
    __shared__ float red0[128], red1[128];
    float a0 = 0.f, a1 = 0.f;
    for (int dd = tid; dd < 1024; dd += 128) {
        float cv = (dd < 512) ? sel[dd] : gen[dd - 512];
        a0 += cv * fcW[dd];
        a1 += cv * fcW[1024 + dd];
    }
    red0[tid] = a0; red1[tid] = a1; __syncthreads();
    for (int st = 64; st > 0; st >>= 1) {
        if (tid < st) { red0[tid] += red0[tid + st]; red1[tid] += red1[tid + st]; }
        __syncthreads();
    }
    if (tid == 0) {
        out[b * 2 + 0] = red0[0] + fcb[0];
        out[b * 2 + 1] = red1[0] + fcb[1];
    }
}

// ---------------- launch ----------------
extern "C" void kernel_launch(void* const* d_in, const int* in_sizes, int n_in,
                              void* d_out, int out_size)
{
    (void)in_sizes; (void)n_in; (void)out_size;
    const float* x     = (const float*)d_in[0];
    const int*   z     = (const int*)  d_in[1];
    const float* wih_f = (const float*)d_in[2];
    const float* whh_f = (const float*)d_in[3];
    const float* b_f   = (const float*)d_in[4];
    const float* wih_b = (const float*)d_in[5];
    const float* whh_b = (const float*)d_in[6];
    const float* b_b   = (const float*)d_in[7];
    const float* attW  = (const float*)d_in[8];
    const float* attb  = (const float*)d_in[9];
    const float* attv  = (const float*)d_in[10];
    const float* fcW   = (const float*)d_in[11];
    const float* fcb   = (const float*)d_in[12];
    float* out = (float*)d_out;

    cudaFuncSetAttribute(lstm_persist_kernel,
                         cudaFuncAttributeMaxDynamicSharedMemorySize, SMEM_LSTM);

    proj_kernel<<<dim3(80, 128), 256>>>(x, wih_f, wih_b, b_f, b_b);
    lstm_persist_kernel<<<160, 256, SMEM_LSTM>>>(whh_f, whh_b);
    attn_kernel<<<dim3(128, 5), 256>>>(attW, attb, attv);
    softmax_pool_kernel<<<dim3(128, 5), 128>>>();
    copy_out_kernel<<<(NEx * Bdim * H2 + 255) / 256, 256>>>(out);
    final_kernel<<<128, 128>>>(z, fcW, fcb, out);
}

// round 4
// speedup vs baseline: 1.5695x; 1.0009x over previous
#include <cuda_runtime.h>
#include <math.h>

#define Ldim 128
#define Bdim 128
#define Vdim 300
#define Hdim 256
#define NEx  5
#define NCh  10      // 5 experts x 2 directions
#define G4   1024    // 4*H
#define H2   512     // 2*H

// ---------------- device scratch (no allocations allowed) ----------------
__device__ float g_PROJ[(size_t)NCh * Ldim * Bdim * G4];   // [c][t][b][g]
__device__ float g_HS[(size_t)NEx * Bdim * Ldim * H2];     // [e][b][l][2H]
__device__ float g_Hst[2][(size_t)NCh * Bdim * Hdim];      // double-buffered h state
__device__ float g_s[(size_t)NEx * Bdim * Ldim];           // attention logits
__device__ float g_OUT[(size_t)NEx * Bdim * H2];           // pooled outputs
__device__ unsigned int g_bar_arrive[NCh];                 // zero-init
__device__ unsigned int g_bar_gen[NCh];                    // monotonically increasing

// ---------------- helpers ----------------
__device__ __forceinline__ float sigf(float x) { return 1.0f / (1.0f + __expf(-x)); }
__device__ __forceinline__ float tanh_fast(float x) {
    float cx = fminf(fmaxf(x, -15.0f), 15.0f);
    float e = __expf(2.0f * cx);
    return (e - 1.0f) / (e + 1.0f);
}
__device__ __forceinline__ unsigned long long packf2(float lo, float hi) {
    unsigned long long r;
    asm("mov.b64 %0, {%1,%2};" : "=l"(r) : "f"(lo), "f"(hi));
    return r;
}
__device__ __forceinline__ float2 unpackf2(unsigned long long v) {
    float2 p;
    asm("mov.b64 {%0,%1}, %2;" : "=f"(p.x), "=f"(p.y) : "l"(v));
    return p;
}
__device__ __forceinline__ void fmaf2(unsigned long long& d, unsigned long long a, unsigned long long b) {
    asm("fma.rn.f32x2 %0, %1, %2, %0;" : "+l"(d) : "l"(a), "l"(b));
}

// ---------------- input projection GEMM (FFMA2) ----------------
__global__ __launch_bounds__(256) void proj_kernel(
    const float* __restrict__ x,
    const float* __restrict__ wf, const float* __restrict__ wb,
    const float* __restrict__ bf, const float* __restrict__ bb)
{
    __shared__ float As[16][128];
    __shared__ float Bs[16][128];

    const int m0 = blockIdx.y * 128;
    const int n0 = blockIdx.x * 128;
    const int tid = threadIdx.x;
    const int tx = tid & 15, ty = tid >> 4;

    const int c = n0 >> 10;
    const int e = c >> 1, d = c & 1;
    const float* wbase = (d ? wb : wf) + (size_t)e * G4 * Vdim;
    const int g0 = n0 & 1023;

    unsigned long long acc2[4][8];
#pragma unroll
    for (int i = 0; i < 4; i++)
#pragma unroll
        for (int j = 0; j < 8; j++) acc2[i][j] = 0ull;

    for (int k0 = 0; k0 < Vdim; k0 += 16) {
        {
            int i = tid * 8;
            int mm = i >> 4, kk = i & 15;
            const float* xrow = x + (size_t)(m0 + mm) * Vdim + k0;
#pragma unroll
            for (int j = 0; j < 8; j++) {
                float v = (k0 + kk + j < Vdim) ? xrow[kk + j] : 0.0f;
                As[kk + j][mm] = v;
            }
        }
        {
            int i = tid * 8;
            int nn = i >> 4, kk = i & 15;
            const float* wrow = wbase + (size_t)(g0 + nn) * Vdim + k0;
#pragma unroll
            for (int j = 0; j < 8; j++) {
                float v = (k0 + kk + j < Vdim) ? wrow[kk + j] : 0.0f;
                Bs[kk + j][nn] = v;
            }
        }
        __syncthreads();
#pragma unroll
        for (int k = 0; k < 16; k++) {
            unsigned long long a2[4], b2[8];
            const unsigned long long* arow = (const unsigned long long*)&As[k][ty * 8];
#pragma unroll
            for (int i = 0; i < 4; i++) a2[i] = arow[i];
#pragma unroll
            for (int j = 0; j < 8; j++) {
                float bw = Bs[k][tx * 8 + j];
                b2[j] = packf2(bw, bw);
            }
#pragma unroll
            for (int i = 0; i < 4; i++)
#pragma unroll
                for (int j = 0; j < 8; j++) fmaf2(acc2[i][j], a2[i], b2[j]);
        }
        __syncthreads();
    }

    const float* bias = (d ? bb : bf) + (size_t)e * G4;
    float bv[8];
#pragma unroll
    for (int j = 0; j < 8; j++) bv[j] = bias[g0 + tx * 8 + j];

    const int b_i = m0 >> 7;
#pragma unroll
    for (int i = 0; i < 4; i++) {
        int l0 = ty * 8 + 2 * i;
        int t_a = d ? (Ldim - 1 - l0) : l0;
        int t_b = d ? (Ldim - 1 - (l0 + 1)) : (l0 + 1);
        float* dstA = g_PROJ + (((size_t)c * Ldim + t_a) * Bdim + b_i) * G4 + g0 + tx * 8;
        float* dstB = g_PROJ + (((size_t)c * Ldim + t_b) * Bdim + b_i) * G4 + g0 + tx * 8;
#pragma unroll
        for (int j = 0; j < 8; j++) {
            float2 v = unpackf2(acc2[i][j]);
            dstA[j] = v.x + bv[j];
            dstB[j] = v.y + bv[j];
        }
    }
}

// ---------------- persistent LSTM recurrence (grid 80 = 10 chains x 8 slices) ----------------
// Each CTA owns 32 h-dims (128 gate cols), W slice cached in SMEM (129-padded),
// c-state in registers, 8-CTA chain barrier per step. One CTA per SM -> no stragglers.
#define WS_STRIDE 129
#define SMEM_LSTM ((256 * WS_STRIDE + 2 * 32 * 132) * 4)   // 165,888 bytes

__global__ __launch_bounds__(256, 1) void lstm_persist_kernel(
    const float* __restrict__ whf, const float* __restrict__ whb)
{
    extern __shared__ float sm[];
    float* Ws = sm;                          // [k=256][col=128] stride 129
    float* Hs0 = sm + 256 * WS_STRIDE;       // [32][132]
    float* Hs1 = Hs0 + 32 * 132;

    const int bid = blockIdx.x;
    const int c = bid >> 3, p = bid & 7;
    const int hd0 = p * 32;
    const int e = c >> 1, d = c & 1;
    const float* wbase = (d ? whb : whf) + (size_t)e * G4 * Hdim;

    const int tid = threadIdx.x;
    const int tx = tid & 15, ty = tid >> 4;

    // ---- load W slice into SMEM once: col = g*32 + u  <-  row g*256 + hd0 + u ----
    for (int idx = tid; idx < 128 * 64; idx += 256) {
        int col = idx >> 6;          // 0..127
        int k4 = idx & 63;           // float4 index within 256-k row
        int g = col >> 5, u = col & 31;
        float4 w = *(const float4*)(wbase + (size_t)(g * 256 + hd0 + u) * Hdim + k4 * 4);
        Ws[(k4 * 4 + 0) * WS_STRIDE + col] = w.x;
        Ws[(k4 * 4 + 1) * WS_STRIDE + col] = w.y;
        Ws[(k4 * 4 + 2) * WS_STRIDE + col] = w.z;
        Ws[(k4 * 4 + 3) * WS_STRIDE + col] = w.w;
    }

    unsigned int bgen = 0;
    if (tid == 0) bgen = *(volatile unsigned int*)&g_bar_gen[c];
    __syncthreads();

    // c-state: 8 batch rows x 2 hd per thread = 16 values
    float cst[16];
#pragma unroll
    for (int i = 0; i < 16; i++) cst[i] = 0.0f;

    const int mrow = tid >> 1;     // 0..127 batch row for H-tile loading
    const int kh = tid & 1;        // 16-k half

    for (int t = 0; t < Ldim; t++) {
        // ---- accumulators init from PROJ (bias folded in) ----
        // acc2[i][g*2+j] packs (batch b, b+1) for gate g, hd = hd0 + tx*2 + j
        unsigned long long acc2[4][8];
        const float* projb = g_PROJ + (((size_t)c * Ldim + t) * Bdim) * G4;
#pragma unroll
        for (int i = 0; i < 4; i++) {
            int b = ty * 8 + 2 * i;
            const float* qa = projb + (size_t)b * G4 + hd0 + tx * 2;
            const float* qb = qa + G4;
#pragma unroll
            for (int g = 0; g < 4; g++) {
                float2 va = __ldcg((const float2*)(qa + g * Hdim));
                float2 vb = __ldcg((const float2*)(qb + g * Hdim));
                acc2[i][g * 2 + 0] = packf2(va.x, vb.x);
                acc2[i][g * 2 + 1] = packf2(va.y, vb.y);
            }
        }

        if (t > 0) {
            const float* Hp = g_Hst[t & 1] + (size_t)c * Bdim * Hdim;
            {
                const float4* src = (const float4*)(Hp + (size_t)mrow * Hdim + kh * 16);
                float4 f0 = __ldcg(src), f1 = __ldcg(src + 1), f2 = __ldcg(src + 2), f3 = __ldcg(src + 3);
                float* hb = Hs0;
                int kb = kh * 16;
                hb[(kb + 0) * 132 + mrow] = f0.x; hb[(kb + 1) * 132 + mrow] = f0.y;
                hb[(kb + 2) * 132 + mrow] = f0.z; hb[(kb + 3) * 132 + mrow] = f0.w;
                hb[(kb + 4) * 132 + mrow] = f1.x; hb[(kb + 5) * 132 + mrow] = f1.y;
                hb[(kb + 6) * 132 + mrow] = f1.z; hb[(kb + 7) * 132 + mrow] = f1.w;
                hb[(kb + 8) * 132 + mrow] = f2.x; hb[(kb + 9) * 132 + mrow] = f2.y;
                hb[(kb + 10) * 132 + mrow] = f2.z; hb[(kb + 11) * 132 + mrow] = f2.w;
                hb[(kb + 12) * 132 + mrow] = f3.x; hb[(kb + 13) * 132 + mrow] = f3.y;
                hb[(kb + 14) * 132 + mrow] = f3.z; hb[(kb + 15) * 132 + mrow] = f3.w;
            }
            __syncthreads();
            for (int kt = 0; kt < 8; kt++) {
                float4 f0, f1, f2, f3;
                if (kt < 7) {
                    const float4* src = (const float4*)(Hp + (size_t)mrow * Hdim + (kt + 1) * 32 + kh * 16);
                    f0 = __ldcg(src); f1 = __ldcg(src + 1); f2 = __ldcg(src + 2); f3 = __ldcg(src + 3);
                }
                const float* hb = (kt & 1) ? Hs1 : Hs0;
                const float* wk = Ws + kt * 32 * WS_STRIDE;
#pragma unroll 4
                for (int kk = 0; kk < 32; kk++) {
                    const float* hr = hb + kk * 132 + ty * 8;
                    unsigned long long a2[4];
#pragma unroll
                    for (int i = 0; i < 4; i++)
                        a2[i] = *(const unsigned long long*)(hr + 2 * i);
                    const float* wr = wk + kk * WS_STRIDE + tx * 2;
#pragma unroll
                    for (int g = 0; g < 4; g++) {
#pragma unroll
                        for (int j = 0; j < 2; j++) {
                            float bw = wr[g * 32 + j];
                            unsigned long long b2 = packf2(bw, bw);
#pragma unroll
                            for (int i = 0; i < 4; i++) fmaf2(acc2[i][g * 2 + j], a2[i], b2);
                        }
                    }
                }
                if (kt < 7) {
                    float* hb2 = (kt & 1) ? Hs0 : Hs1;
                    int kb = kh * 16;
                    hb2[(kb + 0) * 132 + mrow] = f0.x; hb2[(kb + 1) * 132 + mrow] = f0.y;
                    hb2[(kb + 2) * 132 + mrow] = f0.z; hb2[(kb + 3) * 132 + mrow] = f0.w;
                    hb2[(kb + 4) * 132 + mrow] = f1.x; hb2[(kb + 5) * 132 + mrow] = f1.y;
                    hb2[(kb + 6) * 132 + mrow] = f1.z; hb2[(kb + 7) * 132 + mrow] = f1.w;
                    hb2[(kb + 8) * 132 + mrow] = f2.x; hb2[(kb + 9) * 132 + mrow] = f2.y;
                    hb2[(kb + 10) * 132 + mrow] = f2.z; hb2[(kb + 11) * 132 + mrow] = f2.w;
                    hb2[(kb + 12) * 132 + mrow] = f3.x; hb2[(kb + 13) * 132 + mrow] = f3.y;
                    hb2[(kb + 14) * 132 + mrow] = f3.z; hb2[(kb + 15) * 132 + mrow] = f3.w;
                }
                __syncthreads();
            }
        }

        // ---- pointwise LSTM update; write h (float2 per row) ----
        float* Hn = g_Hst[(t & 1) ^ 1] + (size_t)c * Bdim * Hdim;
        const int lo = d ? (Ldim - 1 - t) : t;
        const int hdc = hd0 + tx * 2;
#pragma unroll
        for (int i = 0; i < 4; i++) {
            int b = ty * 8 + 2 * i;
            float2 A[8];
#pragma unroll
            for (int q = 0; q < 8; q++) A[q] = unpackf2(acc2[i][q]);
            // batch row b (x-lanes), row b+1 (y-lanes); gate order i,f,g,o; j = hd sub-index
            float2 hb0, hb1;
            {
                float cn = sigf(A[2].x) * cst[i * 4 + 0] + sigf(A[0].x) * tanh_fast(A[4].x);
                cst[i * 4 + 0] = cn;
                hb0.x = sigf(A[6].x) * tanh_fast(cn);
            }
            {
                float cn = sigf(A[3].x) * cst[i * 4 + 1] + sigf(A[1].x) * tanh_fast(A[5].x);
                cst[i * 4 + 1] = cn;
                hb0.y = sigf(A[7].x) * tanh_fast(cn);
            }
            {
                float cn = sigf(A[2].y) * cst[i * 4 + 2] + sigf(A[0].y) * tanh_fast(A[4].y);
                cst[i * 4 + 2] = cn;
                hb1.x = sigf(A[6].y) * tanh_fast(cn);
            }
            {
                float cn = sigf(A[3].y) * cst[i * 4 + 3] + sigf(A[1].y) * tanh_fast(A[5].y);
                cst[i * 4 + 3] = cn;
                hb1.y = sigf(A[7].y) * tanh_fast(cn);
            }
            *(float2*)(Hn + (size_t)b * Hdim + hdc) = hb0;
            *(float2*)(Hn + (size_t)(b + 1) * Hdim + hdc) = hb1;
            *(float2*)(g_HS + (((size_t)e * Bdim + b) * Ldim + lo) * H2 + d * Hdim + hdc) = hb0;
            *(float2*)(g_HS + (((size_t)e * Bdim + (b + 1)) * Ldim + lo) * H2 + d * Hdim + hdc) = hb1;
        }

        // ---- chain barrier (8 CTAs) ----
        __threadfence();
        __syncthreads();
        if (tid == 0) {
            unsigned int a = atomicAdd(&g_bar_arrive[c], 1u);
            unsigned int target = bgen + (unsigned)t + 1u;
            if (a == 7u) {
                atomicExch(&g_bar_arrive[c], 0u);
                __threadfence();
                atomicAdd(&g_bar_gen[c], 1u);
            } else {
                while ((int)(*(volatile unsigned int*)&g_bar_gen[c] - target) < 0)
                    __nanosleep(64);
            }
            __threadfence();
        }
        __syncthreads();
    }
}

// ---------------- attention logits (FFMA2) ----------------
__global__ __launch_bounds__(256) void attn_kernel(
    const float* __restrict__ attW, const float* __restrict__ attb,
    const float* __restrict__ attv)
{
    __shared__ float As[16][128];
    __shared__ float Bs[16][128];
    __shared__ float red[128][17];

    const int e = blockIdx.y;
    const int m0 = blockIdx.x * 128;
    const float* Abase = g_HS + (size_t)e * Bdim * Ldim * H2;
    const float* Wbase = attW + (size_t)e * H2 * H2;
    const int tid = threadIdx.x;
    const int tx = tid & 15, ty = tid >> 4;

    float part[8];
#pragma unroll
    for (int r = 0; r < 8; r++) part[r] = 0.0f;

    for (int nc = 0; nc < 4; nc++) {
        const int n0 = nc * 128;
        unsigned long long acc2[4][8];
#pragma unroll
        for (int i = 0; i < 4; i++)
#pragma unroll
            for (int j = 0; j < 8; j++) acc2[i][j] = 0ull;

        for (int k0 = 0; k0 < H2; k0 += 16) {
            {
                int i = tid * 8;
                int mm = i >> 4, kk = i & 15;
                const float* arow = Abase + (size_t)(m0 + mm) * H2 + k0;
#pragma unroll
                for (int j = 0; j < 8; j++) As[kk + j][mm] = arow[kk + j];
            }
            {
                int i = tid * 8;
                int nn = i >> 4, kk = i & 15;
                const float* wrow = Wbase + (size_t)(n0 + nn) * H2 + k0;
#pragma unroll
                for (int j = 0; j < 8; j++) Bs[kk + j][nn] = wrow[kk + j];
            }
            __syncthreads();
#pragma unroll
            for (int k = 0; k < 16; k++) {
                unsigned long long a2[4], b2[8];
                const unsigned long long* arow = (const unsigned long long*)&As[k][ty * 8];
#pragma unroll
                for (int i = 0; i < 4; i++) a2[i] = arow[i];
#pragma unroll
                for (int j = 0; j < 8; j++) {
                    float bw = Bs[k][tx * 8 + j];
                    b2[j] = packf2(bw, bw);
                }
#pragma unroll
                for (int i = 0; i < 4; i++)
#pragma unroll
                    for (int j = 0; j < 8; j++) fmaf2(acc2[i][j], a2[i], b2[j]);
            }
            __syncthreads();
        }
#pragma unroll
        for (int j = 0; j < 8; j++) {
            int o = n0 + tx * 8 + j;
            float ab = attb[(size_t)e * H2 + o];
            float av = attv[(size_t)e * H2 + o];
#pragma unroll
            for (int i = 0; i < 4; i++) {
                float2 v = unpackf2(acc2[i][j]);
                part[2 * i] += tanh_fast(v.x + ab) * av;
                part[2 * i + 1] += tanh_fast(v.y + ab) * av;
            }
        }
    }

#pragma unroll
    for (int r = 0; r < 8; r++) red[ty * 8 + r][tx] = part[r];
    __syncthreads();
    if (tid < 128) {
        float ssum = 0.0f;
#pragma unroll
        for (int q = 0; q < 16; q++) ssum += red[tid][q];
        g_s[(size_t)e * Bdim * Ldim + m0 + tid] = ssum;
    }
}

// ---------------- softmax over L + weighted pooling ----------------
__global__ __launch_bounds__(128) void softmax_pool_kernel()
{
    const int e = blockIdx.y, b = blockIdx.x;
    __shared__ float wts[Ldim];
    __shared__ float red[128];
    const int tid = threadIdx.x;

    float v = g_s[((size_t)e * Bdim + b) * Ldim + tid];
    red[tid] = v; __syncthreads();
    for (int st = 64; st > 0; st >>= 1) {
        if (tid < st) red[tid] = fmaxf(red[tid], red[tid + st]);
        __syncthreads();
    }
    float mx = red[0]; __syncthreads();
    float ev = expf(v - mx);
    red[tid] = ev; __syncthreads();
    for (int st = 64; st > 0; st >>= 1) {
        if (tid < st) red[tid] += red[tid + st];
        __syncthreads();
    }
    float inv = 1.0f / red[0];
    wts[tid] = ev * inv;
    __syncthreads();

    const float* hrow = g_HS + ((size_t)e * Bdim + b) * Ldim * H2;
    float accv[4] = {0.f, 0.f, 0.f, 0.f};
    for (int l = 0; l < Ldim; l++) {
        float a = wts[l];
        const float* hp = hrow + (size_t)l * H2;
#pragma unroll
        for (int j = 0; j < 4; j++) accv[j] += a * hp[tid + j * 128];
    }
    float* op = g_OUT + ((size_t)e * Bdim + b) * H2;
#pragma unroll
    for (int j = 0; j < 4; j++) op[tid + j * 128] = accv[j];
}

// ---------------- output copy: general + specifics ----------------
__global__ void copy_out_kernel(float* __restrict__ out)
{
    int i = blockIdx.x * blockDim.x + threadIdx.x;
    if (i < NEx * Bdim * H2) out[256 + i] = g_OUT[i];
}

// ---------------- gather + final FC ----------------
__global__ __launch_bounds__(128) void final_kernel(
    const int* __restrict__ z, const float* __restrict__ fcW,
    const float* __restrict__ fcb, float* __restrict__ out)
{
    const int b = blockIdx.x;
    const int tid = threadIdx.x;
    const int zi = z[b];
    const float* sel = g_OUT + ((size_t)(1 + zi) * Bdim + b) * H2;
    const float* gen = g_OUT + (size_t)b * H2;
    __shared__ float red0[128], red1[128];
    float a0 = 0.f, a1 = 0.f;
    for (int dd = tid; dd < 1024; dd += 128) {
        float cv = (dd < 512) ? sel[dd] : gen[dd - 512];
        a0 += cv * fcW[dd];
        a1 += cv * fcW[1024 + dd];
    }
    red0[tid] = a0; red1[tid] = a1; __syncthreads();
    for (int st = 64; st > 0; st >>= 1) {
        if (tid < st) { red0[tid] += red0[tid + st]; red1[tid] += red1[tid + st]; }
        __syncthreads();
    }
    if (tid == 0) {
        out[b * 2 + 0] = red0[0] + fcb[0];
        out[b * 2 + 1] = red1[0] + fcb[1];
    }
}

// ---------------- launch ----------------
extern "C" void kernel_launch(void* const* d_in, const int* in_sizes, int n_in,
                              void* d_out, int out_size)
{
    (void)in_sizes; (void)n_in; (void)out_size;
    const float* x     = (const float*)d_in[0];
    const int*   z     = (const int*)  d_in[1];
    const float* wih_f = (const float*)d_in[2];
    const float* whh_f = (const float*)d_in[3];
    const float* b_f   = (const float*)d_in[4];
    const float* wih_b = (const float*)d_in[5];
    const float* whh_b = (const float*)d_in[6];
    const float* b_b   = (const float*)d_in[7];
    const float* attW  = (const float*)d_in[8];
    const float* attb  = (const float*)d_in[9];
    const float* attv  = (const float*)d_in[10];
    const float* fcW   = (const float*)d_in[11];
    const float* fcb   = (const float*)d_in[12];
    float* out = (float*)d_out;

    cudaFuncSetAttribute(lstm_persist_kernel,
                         cudaFuncAttributeMaxDynamicSharedMemorySize, SMEM_LSTM);

    proj_kernel<<<dim3(80, 128), 256>>>(x, wih_f, wih_b, b_f, b_b);
    lstm_persist_kernel<<<80, 256, SMEM_LSTM>>>(whh_f, whh_b);
    attn_kernel<<<dim3(128, 5), 256>>>(attW, attb, attv);
    softmax_pool_kernel<<<dim3(128, 5), 128>>>();
    copy_out_kernel<<<(NEx * Bdim * H2 + 255) / 256, 256>>>(out);
    final_kernel<<<128, 128>>>(z, fcW, fcb, out);
}

// round 7
// speedup vs baseline: 2.3465x; 1.4950x over previous
#include <cuda_runtime.h>
#include <cuda_bf16.h>
#include <cstdint>
#include <stdint.h>
#include <math.h>

#define Ldim 128
#define Bdim 128
#define Vdim 300
#define Hdim 256
#define NEx  5
#define NCh  10      // 5 experts x 2 directions
#define G4   1024    // 4*H
#define H2   512     // 2*H
#define KPP  960     // proj K: 3 x 320 (hi, hi, lo sections)
#define KPA  1536    // attn K: 3 x 512

// ---------------- device scratch (no allocations allowed) ----------------
__device__ float g_PROJ[(size_t)NCh * Ldim * Bdim * G4];   // [c][t][b][g]
__device__ float g_HS[(size_t)NEx * Bdim * Ldim * H2];     // [e][b][l][2H]
__device__ float g_Hst[2][(size_t)NCh * Bdim * Hdim];      // double-buffered h state
__device__ float g_s[(size_t)NEx * Bdim * Ldim];           // attention logits
__device__ float g_OUT[(size_t)NEx * Bdim * H2];           // pooled outputs
__device__ unsigned int g_bar_arrive[NCh];
__device__ unsigned int g_bar_gen[NCh];

// bf16 split GEMM operands
__device__ __nv_bfloat16 g_pA[(size_t)16384 * KPP];        // proj A' [m][960]
__device__ __nv_bfloat16 g_pB[(size_t)10240 * KPP];        // proj B' [n][960]
__device__ __nv_bfloat16 g_aA[(size_t)NEx * 16384 * 1024]; // attn A: [e][m][hi512|lo512]
__device__ __nv_bfloat16 g_aB[(size_t)NEx * H2 * KPA];     // attn B' [e][o][whi|wlo|whi]

// ---------------- helpers ----------------
__device__ __forceinline__ float sigf(float x) { return 1.0f / (1.0f + __expf(-x)); }
__device__ __forceinline__ float tanh_fast(float x) {
    float cx = fminf(fmaxf(x, -15.0f), 15.0f);
    float e = __expf(2.0f * cx);
    return (e - 1.0f) / (e + 1.0f);
}
__device__ __forceinline__ unsigned long long packf2(float lo, float hi) {
    unsigned long long r;
    asm("mov.b64 %0, {%1,%2};" : "=l"(r) : "f"(lo), "f"(hi));
    return r;
}
__device__ __forceinline__ float2 unpackf2(unsigned long long v) {
    float2 p;
    asm("mov.b64 {%0,%1}, %2;" : "=f"(p.x), "=f"(p.y) : "l"(v));
    return p;
}
__device__ __forceinline__ void fmaf2(unsigned long long& d, unsigned long long a, unsigned long long b) {
    asm("fma.rn.f32x2 %0, %1, %2, %0;" : "+l"(d) : "l"(a), "l"(b));
}
__device__ __forceinline__ unsigned atom_add_release(unsigned* p, unsigned v) {
    unsigned old;
    asm volatile("atom.release.gpu.global.add.u32 %0, [%1], %2;"
                 : "=r"(old) : "l"(p), "r"(v) : "memory");
    return old;
}
__device__ __forceinline__ unsigned ld_acquire(const unsigned* p) {
    unsigned v;
    asm volatile("ld.acquire.gpu.global.u32 %0, [%1];" : "=r"(v) : "l"(p) : "memory");
    return v;
}
// m16n8k16 bf16 mma, fp32 accum (baseline PTX, compiles for compute_103)
__device__ __forceinline__ void mma16816(float* c, const uint32_t* a, const uint32_t* b) {
    asm volatile(
        "mma.sync.aligned.m16n8k16.row.col.f32.bf16.bf16.f32 "
        "{%0,%1,%2,%3}, {%4,%5,%6,%7}, {%8,%9}, {%0,%1,%2,%3};"
        : "+f"(c[0]), "+f"(c[1]), "+f"(c[2]), "+f"(c[3])
        : "r"(a[0]), "r"(a[1]), "r"(a[2]), "r"(a[3]), "r"(b[0]), "r"(b[1]));
}

// ---------------- prep: proj operands (3-term split, padded K) ----------------
__global__ __launch_bounds__(256) void prep_proj_kernel(
    const float* __restrict__ x,
    const float* __restrict__ wf, const float* __restrict__ wb)
{
    const int row = blockIdx.x;
    const int tid = threadIdx.x;
    if (row < 16384) {
        const float* src = x + (size_t)row * Vdim;
        __nv_bfloat16* dA = g_pA + (size_t)row * KPP;
        for (int col = tid; col < KPP; col += 256) {
            int s = col / 320, kk = col - s * 320;
            float v = (kk < Vdim) ? src[kk] : 0.0f;
            __nv_bfloat16 hi = __float2bfloat16(v);
            dA[col] = (s < 2) ? hi : __float2bfloat16(v - __bfloat162float(hi));
        }
    } else {
        const int n = row - 16384;
        const int c = n >> 10, e = c >> 1, d = c & 1;
        const int gg = n & 1023;
        const float* src = (d ? wb : wf) + ((size_t)e * G4 + gg) * Vdim;
        __nv_bfloat16* dB = g_pB + (size_t)n * KPP;
        for (int col = tid; col < KPP; col += 256) {
            int s = col / 320, kk = col - s * 320;
            float v = (kk < Vdim) ? src[kk] : 0.0f;
            __nv_bfloat16 hi = __float2bfloat16(v);
            dB[col] = (s == 1) ? __float2bfloat16(v - __bfloat162float(hi)) : hi;
        }
    }
}

// ---------------- prep: attn B' (whi | wlo | whi) ----------------
__global__ __launch_bounds__(256) void prep_attnB_kernel(const float* __restrict__ attW)
{
    const int r = blockIdx.x;                 // e*512 + o
    const int tid = threadIdx.x;
    const float* src = attW + (size_t)r * H2;
    __nv_bfloat16* dB = g_aB + (size_t)r * KPA;
    for (int col = tid; col < KPA; col += 256) {
        int s = col >> 9, kk = col & 511;
        float v = src[kk];
        __nv_bfloat16 hi = __float2bfloat16(v);
        dB[col] = (s == 1) ? __float2bfloat16(v - __bfloat162float(hi)) : hi;
    }
}

// ---------------- prep: attn A (hi | lo of g_HS) ----------------
__global__ __launch_bounds__(256) void prep_attnA_kernel()
{
    const int r = blockIdx.x;                 // e*16384 + m
    const int tid = threadIdx.x;
    const float* src = g_HS + (size_t)r * H2;
    __nv_bfloat16* dA = g_aA + (size_t)r * 1024;
    for (int col = tid; col < 1024; col += 256) {
        int kk = col & 511;
        float v = src[kk];
        __nv_bfloat16 hi = __float2bfloat16(v);
        dA[col] = (col < 512) ? hi : __float2bfloat16(v - __bfloat162float(hi));
    }
}

// ---------------- proj GEMM (mma.sync bf16) ----------------
// M=16384 (b*128+l), N=10240 gate cols, K=960. CTA tile 128x128, 8 warps 2x4.
__global__ __launch_bounds__(256) void proj_mma_kernel(
    const float* __restrict__ bf, const float* __restrict__ bb)
{
    __shared__ __align__(16) uint32_t As[128][36];
    __shared__ __align__(16) uint32_t Bs[128][36];
    __shared__ float biasS[128];

    const int tid = threadIdx.x;
    const int warp = tid >> 5, lane = tid & 31;
    const int g = lane >> 2, tg = lane & 3;
    const int warp_m = (warp >> 2) * 64;
    const int warp_n = (warp & 3) * 32;

    const int n0 = blockIdx.x * 128;
    const int m0 = blockIdx.y * 128;
    const int b_i = blockIdx.y;
    const int c = n0 >> 10, e = c >> 1, d = c & 1;
    const int g0 = n0 & 1023;

    {
        const float* bias = (d ? bb : bf) + (size_t)e * G4;
        if (tid < 128) biasS[tid] = bias[g0 + tid];
    }

    float acc[4][4][4];
#pragma unroll
    for (int m = 0; m < 4; m++)
#pragma unroll
        for (int n = 0; n < 4; n++)
#pragma unroll
            for (int q = 0; q < 4; q++) acc[m][n][q] = 0.0f;

    const uint4* Ag = (const uint4*)g_pA;     // 120 uint4 per row
    const uint4* Bg = (const uint4*)g_pB;

    for (int kc = 0; kc < 15; kc++) {
#pragma unroll
        for (int q = 0; q < 4; q++) {
            int idx = tid + q * 256;
            int r = idx >> 3, ju = idx & 7;
            *(uint4*)&As[r][ju * 4] = Ag[(size_t)(m0 + r) * 120 + kc * 8 + ju];
            *(uint4*)&Bs[r][ju * 4] = Bg[(size_t)(n0 + r) * 120 + kc * 8 + ju];
        }
        __syncthreads();
#pragma unroll
        for (int ks = 0; ks < 4; ks++) {
            uint32_t af[4][4], bfr[4][2];
#pragma unroll
            for (int m = 0; m < 4; m++) {
                int r0 = warp_m + m * 16 + g;
                af[m][0] = As[r0][ks * 8 + tg];
                af[m][1] = As[r0 + 8][ks * 8 + tg];
                af[m][2] = As[r0][ks * 8 + tg + 4];
                af[m][3] = As[r0 + 8][ks * 8 + tg + 4];
            }
#pragma unroll
            for (int n = 0; n < 4; n++) {
                int rn = warp_n + n * 8 + g;
                bfr[n][0] = Bs[rn][ks * 8 + tg];
                bfr[n][1] = Bs[rn][ks * 8 + tg + 4];
            }
#pragma unroll
            for (int m = 0; m < 4; m++)
#pragma unroll
                for (int n = 0; n < 4; n++) mma16816(acc[m][n], af[m], bfr[n]);
        }
        __syncthreads();
    }

    // epilogue: +bias, scatter rows (seq pos, time-reversed for backward chains)
#pragma unroll
    for (int m = 0; m < 4; m++) {
        int l0 = warp_m + m * 16 + g;
        int l1 = l0 + 8;
        int t0 = d ? (Ldim - 1 - l0) : l0;
        int t1 = d ? (Ldim - 1 - l1) : l1;
        float* base0 = g_PROJ + (((size_t)c * Ldim + t0) * Bdim + b_i) * G4 + g0 + warp_n;
        float* base1 = g_PROJ + (((size_t)c * Ldim + t1) * Bdim + b_i) * G4 + g0 + warp_n;
#pragma unroll
        for (int n = 0; n < 4; n++) {
            int cc = n * 8 + 2 * tg;
            float2 v0 = { acc[m][n][0] + biasS[warp_n + cc],
                          acc[m][n][1] + biasS[warp_n + cc + 1] };
            float2 v1 = { acc[m][n][2] + biasS[warp_n + cc],
                          acc[m][n][3] + biasS[warp_n + cc + 1] };
            *(float2*)(base0 + cc) = v0;
            *(float2*)(base1 + cc) = v1;
        }
    }
}

// ---------------- attention logits GEMM (mma.sync bf16) ----------------
// Per CTA: 128 rows of expert e, loops 4 N-tiles of 128, K=1536 (3 passes of 512).
__global__ __launch_bounds__(256) void attn_mma_kernel(
    const float* __restrict__ attb, const float* __restrict__ attv)
{
    __shared__ __align__(16) uint32_t As[128][36];
    __shared__ __align__(16) uint32_t Bs[128][36];
    __shared__ float red[128][17];

    const int tid = threadIdx.x;
    const int warp = tid >> 5, lane = tid & 31;
    const int g = lane >> 2, tg = lane & 3;
    const int warp_m = (warp >> 2) * 64;
    const int warp_n = (warp & 3) * 32;

    const int m0 = blockIdx.x * 128;
    const int e = blockIdx.y;

    const uint4* Ag = (const uint4*)g_aA;     // 128 uint4 per row (1024 bf16)
    const uint4* Bg = (const uint4*)g_aB;     // 192 uint4 per row (1536 bf16)
    const float* abp = attb + (size_t)e * H2;
    const float* avp = attv + (size_t)e * H2;

    float part[4][2];
#pragma unroll
    for (int m = 0; m < 4; m++) { part[m][0] = 0.0f; part[m][1] = 0.0f; }

    for (int nc = 0; nc < 4; nc++) {
        const int n0 = nc * 128;
        float acc[4][4][4];
#pragma unroll
        for (int m = 0; m < 4; m++)
#pragma unroll
            for (int n = 0; n < 4; n++)
#pragma unroll
                for (int q = 0; q < 4; q++) acc[m][n][q] = 0.0f;

        for (int kc = 0; kc < 24; kc++) {
            const int p = kc >> 3, within = kc & 7;
            const int au4 = (p == 2 ? 64 : 0) + within * 8;  // uint4 offset in A row
            const int bu4 = kc * 8;                          // uint4 offset in B row
#pragma unroll
            for (int q = 0; q < 4; q++) {
                int idx = tid + q * 256;
                int r = idx >> 3, ju = idx & 7;
                *(uint4*)&As[r][ju * 4] =
                    Ag[((size_t)e * 16384 + m0 + r) * 128 + au4 + ju];
                *(uint4*)&Bs[r][ju * 4] =
                    Bg[((size_t)e * H2 + n0 + r) * 192 + bu4 + ju];
            }
            __syncthreads();
#pragma unroll
            for (int ks = 0; ks < 4; ks++) {
                uint32_t af[4][4], bfr[4][2];
#pragma unroll
                for (int m = 0; m < 4; m++) {
                    int r0 = warp_m + m * 16 + g;
                    af[m][0] = As[r0][ks * 8 + tg];
                    af[m][1] = As[r0 + 8][ks * 8 + tg];
                    af[m][2] = As[r0][ks * 8 + tg + 4];
                    af[m][3] = As[r0 + 8][ks * 8 + tg + 4];
                }
#pragma unroll
                for (int n = 0; n < 4; n++) {
                    int rn = warp_n + n * 8 + g;
                    bfr[n][0] = Bs[rn][ks * 8 + tg];
                    bfr[n][1] = Bs[rn][ks * 8 + tg + 4];
                }
#pragma unroll
                for (int m = 0; m < 4; m++)
#pragma unroll
                    for (int n = 0; n < 4; n++) mma16816(acc[m][n], af[m], bfr[n]);
            }
            __syncthreads();
        }

        // fused epilogue: tanh(+attb) * attv, accumulate per-row partials
#pragma unroll
        for (int n = 0; n < 4; n++) {
            int o = n0 + warp_n + n * 8 + 2 * tg;
            float ab0 = abp[o], ab1 = abp[o + 1];
            float av0 = avp[o], av1 = avp[o + 1];
#pragma unroll
            for (int m = 0; m < 4; m++) {
                part[m][0] += tanh_fast(acc[m][n][0] + ab0) * av0
                            + tanh_fast(acc[m][n][1] + ab1) * av1;
                part[m][1] += tanh_fast(acc[m][n][2] + ab0) * av0
                            + tanh_fast(acc[m][n][3] + ab1) * av1;
            }
        }
    }

    // reduce 16 partials per row
#pragma unroll
    for (int m = 0; m < 4; m++) {
        int r0 = warp_m + m * 16 + g;
        red[r0][(warp & 3) * 4 + tg] = part[m][0];
        red[r0 + 8][(warp & 3) * 4 + tg] = part[m][1];
    }
    __syncthreads();
    if (tid < 128) {
        float s = 0.0f;
#pragma unroll
        for (int q = 0; q < 16; q++) s += red[tid][q];
        g_s[(size_t)e * Bdim * Ldim + m0 + tid] = s;
    }
}

// ---------------- persistent LSTM recurrence (grid 80 = 10 chains x 8 slices) ----------------
#define WS_STRIDE 129
#define SMEM_LSTM ((256 * WS_STRIDE + 2 * 32 * 132) * 4)   // 165,888 bytes

__global__ __launch_bounds__(256, 1) void lstm_persist_kernel(
    const float* __restrict__ whf, const float* __restrict__ whb)
{
    extern __shared__ float sm[];
    float* Ws = sm;
    float* Hs0 = sm + 256 * WS_STRIDE;
    float* Hs1 = Hs0 + 32 * 132;

    const int bid = blockIdx.x;
    const int c = bid >> 3, p = bid & 7;
    const int hd0 = p * 32;
    const int e = c >> 1, d = c & 1;
    const float* wbase = (d ? whb : whf) + (size_t)e * G4 * Hdim;

    const int tid = threadIdx.x;
    const int tx = tid & 15, ty = tid >> 4;

    for (int idx = tid; idx < 128 * 64; idx += 256) {
        int col = idx >> 6;
        int k4 = idx & 63;
        int g = col >> 5, u = col & 31;
        float4 w = *(const float4*)(wbase + (size_t)(g * 256 + hd0 + u) * Hdim + k4 * 4);
        Ws[(k4 * 4 + 0) * WS_STRIDE + col] = w.x;
        Ws[(k4 * 4 + 1) * WS_STRIDE + col] = w.y;
        Ws[(k4 * 4 + 2) * WS_STRIDE + col] = w.z;
        Ws[(k4 * 4 + 3) * WS_STRIDE + col] = w.w;
    }

    unsigned int bgen = 0;
    if (tid == 0) bgen = ld_acquire(&g_bar_gen[c]);
    __syncthreads();

    float cst[16];
#pragma unroll
    for (int i = 0; i < 16; i++) cst[i] = 0.0f;

    const int mrow = tid >> 1;
    const int kh = tid & 1;

    for (int t = 0; t < Ldim; t++) {
        unsigned long long acc2[4][8];
        const float* projb = g_PROJ + (((size_t)c * Ldim + t) * Bdim) * G4;
#pragma unroll
        for (int i = 0; i < 4; i++) {
            int b = ty * 8 + 2 * i;
            const float* qa = projb + (size_t)b * G4 + hd0 + tx * 2;
            const float* qb = qa + G4;
#pragma unroll
            for (int g = 0; g < 4; g++) {
                float2 va = __ldcg((const float2*)(qa + g * Hdim));
                float2 vb = __ldcg((const float2*)(qb + g * Hdim));
                acc2[i][g * 2 + 0] = packf2(va.x, vb.x);
                acc2[i][g * 2 + 1] = packf2(va.y, vb.y);
            }
        }

        if (t > 0) {
            const float* Hp = g_Hst[t & 1] + (size_t)c * Bdim * Hdim;
            {
                const float4* src = (const float4*)(Hp + (size_t)mrow * Hdim + kh * 16);
                float4 f0 = __ldcg(src), f1 = __ldcg(src + 1), f2 = __ldcg(src + 2), f3 = __ldcg(src + 3);
                float* hb = Hs0;
                int kb = kh * 16;
                hb[(kb + 0) * 132 + mrow] = f0.x; hb[(kb + 1) * 132 + mrow] = f0.y;
                hb[(kb + 2) * 132 + mrow] = f0.z; hb[(kb + 3) * 132 + mrow] = f0.w;
                hb[(kb + 4) * 132 + mrow] = f1.x; hb[(kb + 5) * 132 + mrow] = f1.y;
                hb[(kb + 6) * 132 + mrow] = f1.z; hb[(kb + 7) * 132 + mrow] = f1.w;
                hb[(kb + 8) * 132 + mrow] = f2.x; hb[(kb + 9) * 132 + mrow] = f2.y;
                hb[(kb + 10) * 132 + mrow] = f2.z; hb[(kb + 11) * 132 + mrow] = f2.w;
                hb[(kb + 12) * 132 + mrow] = f3.x; hb[(kb + 13) * 132 + mrow] = f3.y;
                hb[(kb + 14) * 132 + mrow] = f3.z; hb[(kb + 15) * 132 + mrow] = f3.w;
            }
            __syncthreads();
            for (int kt = 0; kt < 8; kt++) {
                float4 f0, f1, f2, f3;
                if (kt < 7) {
                    const float4* src = (const float4*)(Hp + (size_t)mrow * Hdim + (kt + 1) * 32 + kh * 16);
                    f0 = __ldcg(src); f1 = __ldcg(src + 1); f2 = __ldcg(src + 2); f3 = __ldcg(src + 3);
                }
                const float* hb = (kt & 1) ? Hs1 : Hs0;
                const float* wk = Ws + kt * 32 * WS_STRIDE;
#pragma unroll 4
                for (int kk = 0; kk < 32; kk++) {
                    const float* hr = hb + kk * 132 + ty * 8;
                    unsigned long long a2[4];
#pragma unroll
                    for (int i = 0; i < 4; i++)
                        a2[i] = *(const unsigned long long*)(hr + 2 * i);
                    const float* wr = wk + kk * WS_STRIDE + tx * 2;
#pragma unroll
                    for (int g = 0; g < 4; g++) {
#pragma unroll
                        for (int j = 0; j < 2; j++) {
                            float bw = wr[g * 32 + j];
                            unsigned long long b2 = packf2(bw, bw);
#pragma unroll
                            for (int i = 0; i < 4; i++) fmaf2(acc2[i][g * 2 + j], a2[i], b2);
                        }
                    }
                }
                if (kt < 7) {
                    float* hb2 = (kt & 1) ? Hs0 : Hs1;
                    int kb = kh * 16;
                    hb2[(kb + 0) * 132 + mrow] = f0.x; hb2[(kb + 1) * 132 + mrow] = f0.y;
                    hb2[(kb + 2) * 132 + mrow] = f0.z; hb2[(kb + 3) * 132 + mrow] = f0.w;
                    hb2[(kb + 4) * 132 + mrow] = f1.x; hb2[(kb + 5) * 132 + mrow] = f1.y;
                    hb2[(kb + 6) * 132 + mrow] = f1.z; hb2[(kb + 7) * 132 + mrow] = f1.w;
                    hb2[(kb + 8) * 132 + mrow] = f2.x; hb2[(kb + 9) * 132 + mrow] = f2.y;
                    hb2[(kb + 10) * 132 + mrow] = f2.z; hb2[(kb + 11) * 132 + mrow] = f2.w;
                    hb2[(kb + 12) * 132 + mrow] = f3.x; hb2[(kb + 13) * 132 + mrow] = f3.y;
                    hb2[(kb + 14) * 132 + mrow] = f3.z; hb2[(kb + 15) * 132 + mrow] = f3.w;
                }
                __syncthreads();
            }
        }

        float* Hn = g_Hst[(t & 1) ^ 1] + (size_t)c * Bdim * Hdim;
        const int lo = d ? (Ldim - 1 - t) : t;
        const int hdc = hd0 + tx * 2;
#pragma unroll
        for (int i = 0; i < 4; i++) {
            int b = ty * 8 + 2 * i;
            float2 A[8];
#pragma unroll
            for (int q = 0; q < 8; q++) A[q] = unpackf2(acc2[i][q]);
            float2 hb0, hb1;
            {
                float cn = sigf(A[2].x) * cst[i * 4 + 0] + sigf(A[0].x) * tanh_fast(A[4].x);
                cst[i * 4 + 0] = cn;
                hb0.x = sigf(A[6].x) * tanh_fast(cn);
            }
            {
                float cn = sigf(A[3].x) * cst[i * 4 + 1] + sigf(A[1].x) * tanh_fast(A[5].x);
                cst[i * 4 + 1] = cn;
                hb0.y = sigf(A[7].x) * tanh_fast(cn);
            }
            {
                float cn = sigf(A[2].y) * cst[i * 4 + 2] + sigf(A[0].y) * tanh_fast(A[4].y);
                cst[i * 4 + 2] = cn;
                hb1.x = sigf(A[6].y) * tanh_fast(cn);
            }
            {
                float cn = sigf(A[3].y) * cst[i * 4 + 3] + sigf(A[1].y) * tanh_fast(A[5].y);
                cst[i * 4 + 3] = cn;
                hb1.y = sigf(A[7].y) * tanh_fast(cn);
            }
            *(float2*)(Hn + (size_t)b * Hdim + hdc) = hb0;
            *(float2*)(Hn + (size_t)(b + 1) * Hdim + hdc) = hb1;
            *(float2*)(g_HS + (((size_t)e * Bdim + b) * Ldim + lo) * H2 + d * Hdim + hdc) = hb0;
            *(float2*)(g_HS + (((size_t)e * Bdim + (b + 1)) * Ldim + lo) * H2 + d * Hdim + hdc) = hb1;
        }

        __syncthreads();
        if (tid == 0) {
            unsigned int a = atom_add_release(&g_bar_arrive[c], 1u);
            unsigned int target = bgen + (unsigned)t + 1u;
            if (a == 7u) {
                g_bar_arrive[c] = 0u;
                atom_add_release(&g_bar_gen[c], 1u);
            } else {
                while ((int)(ld_acquire(&g_bar_gen[c]) - target) < 0)
                    __nanosleep(64);
            }
        }
        __syncthreads();
    }
}

// ---------------- softmax over L + weighted pooling ----------------
__global__ __launch_bounds__(128) void softmax_pool_kernel()
{
    const int e = blockIdx.y, b = blockIdx.x;
    __shared__ float wts[Ldim];
    __shared__ float red[128];
    const int tid = threadIdx.x;

    float v = g_s[((size_t)e * Bdim + b) * Ldim + tid];
    red[tid] = v; __syncthreads();
    for (int st = 64; st > 0; st >>= 1) {
        if (tid < st) red[tid] = fmaxf(red[tid], red[tid + st]);
        __syncthreads();
    }
    float mx = red[0]; __syncthreads();
    float ev = expf(v - mx);
    red[tid] = ev; __syncthreads();
    for (int st = 64; st > 0; st >>= 1) {
        if (tid < st) red[tid] += red[tid + st];
        __syncthreads();
    }
    float inv = 1.0f / red[0];
    wts[tid] = ev * inv;
    __syncthreads();

    const float* hrow = g_HS + ((size_t)e * Bdim + b) * Ldim * H2;
    float accv[4] = {0.f, 0.f, 0.f, 0.f};
    for (int l = 0; l < Ldim; l++) {
        float a = wts[l];
        const float* hp = hrow + (size_t)l * H2;
#pragma unroll
        for (int j = 0; j < 4; j++) accv[j] += a * hp[tid + j * 128];
    }
    float* op = g_OUT + ((size_t)e * Bdim + b) * H2;
#pragma unroll
    for (int j = 0; j < 4; j++) op[tid + j * 128] = accv[j];
}

// ---------------- output copy: general + specifics ----------------
__global__ void copy_out_kernel(float* __restrict__ out)
{
    int i = blockIdx.x * blockDim.x + threadIdx.x;
    if (i < NEx * Bdim * H2) out[256 + i] = g_OUT[i];
}

// ---------------- gather + final FC ----------------
__global__ __launch_bounds__(128) void final_kernel(
    const int* __restrict__ z, const float* __restrict__ fcW,
    const float* __restrict__ fcb, float* __restrict__ out)
{
    const int b = blockIdx.x;
    const int tid = threadIdx.x;
    const int zi = z[b];
    const float* sel = g_OUT + ((size_t)(1 + zi) * Bdim + b) * H2;
    const float* gen = g_OUT + (size_t)b * H2;
    __shared__ float red0[128], red1[128];
    float a0 = 0.f, a1 = 0.f;
    for (int dd = tid; dd < 1024; dd += 128) {
        float cv = (dd < 512) ? sel[dd] : gen[dd - 512];
        a0 += cv * fcW[dd];
        a1 += cv * fcW[1024 + dd];
    }
    red0[tid] = a0; red1[tid] = a1; __syncthreads();
    for (int st = 64; st > 0; st >>= 1) {
        if (tid < st) { red0[tid] += red0[tid + st]; red1[tid] += red1[tid + st]; }
        __syncthreads();
    }
    if (tid == 0) {
        out[b * 2 + 0] = red0[0] + fcb[0];
        out[b * 2 + 1] = red1[0] + fcb[1];
    }
}

// ---------------- launch ----------------
extern "C" void kernel_launch(void* const* d_in, const int* in_sizes, int n_in,
                              void* d_out, int out_size)
{
    (void)in_sizes; (void)n_in; (void)out_size;
    const float* x     = (const float*)d_in[0];
    const int*   z     = (const int*)  d_in[1];
    const float* wih_f = (const float*)d_in[2];
    const float* whh_f = (const float*)d_in[3];
    const float* b_f   = (const float*)d_in[4];
    const float* wih_b = (const float*)d_in[5];
    const float* whh_b = (const float*)d_in[6];
    const float* b_b   = (const float*)d_in[7];
    const float* attW  = (const float*)d_in[8];
    const float* attb  = (const float*)d_in[9];
    const float* attv  = (const float*)d_in[10];
    const float* fcW   = (const float*)d_in[11];
    const float* fcb   = (const float*)d_in[12];
    float* out = (float*)d_out;

    cudaFuncSetAttribute(lstm_persist_kernel,
                         cudaFuncAttributeMaxDynamicSharedMemorySize, SMEM_LSTM);

    prep_proj_kernel<<<16384 + 10240, 256>>>(x, wih_f, wih_b);
    prep_attnB_kernel<<<NEx * H2, 256>>>(attW);
    proj_mma_kernel<<<dim3(80, 128), 256>>>(b_f, b_b);
    lstm_persist_kernel<<<80, 256, SMEM_LSTM>>>(whh_f, whh_b);
    prep_attnA_kernel<<<NEx * 16384, 256>>>();
    attn_mma_kernel<<<dim3(128, 5), 256>>>(attb, attv);
    softmax_pool_kernel<<<dim3(128, 5), 128>>>();
    copy_out_kernel<<<(NEx * Bdim * H2 + 255) / 256, 256>>>(out);
    final_kernel<<<128, 128>>>(z, fcW, fcb, out);
}

// round 9
// speedup vs baseline: 2.9404x; 1.2531x over previous
#include <cuda_runtime.h>
#include <cuda_bf16.h>
#include <cstdint>
#include <stdint.h>
#include <math.h>

#define Ldim 128
#define Bdim 128
#define Vdim 300
#define Hdim 256
#define NEx  5
#define NCh  10      // 5 experts x 2 directions
#define G4   1024    // 4*H
#define H2   512     // 2*H
#define KPP  960     // proj K: 3 x 320 (hi, hi, lo sections)
#define KPA  1536    // attn K: 3 x 512

// ---------------- device scratch (no allocations allowed) ----------------
// NOTE: g_PROJ uses gate-interleaved layout: [c][t][b][cg] with cg = hd*4 + gate.
__device__ float g_PROJ[(size_t)NCh * Ldim * Bdim * G4];
__device__ float g_HS[(size_t)NEx * Bdim * Ldim * H2];     // [e][b][l][2H]
__device__ float g_s[(size_t)NEx * Bdim * Ldim];           // attention logits
__device__ float g_OUT[(size_t)NEx * Bdim * H2];           // pooled outputs
__device__ unsigned int g_bar_arrive[NCh];
__device__ unsigned int g_bar_gen[NCh];

// bf16 split GEMM operands
__device__ __nv_bfloat16 g_pA[(size_t)16384 * KPP];        // proj A' [m][960]
__device__ __nv_bfloat16 g_pB[(size_t)10240 * KPP];        // proj B' [cg-ordered][960]
__device__ __nv_bfloat16 g_aA[(size_t)NEx * 16384 * 1024]; // attn A [e][m][hi512|lo512]
__device__ __nv_bfloat16 g_aB[(size_t)NEx * H2 * KPA];     // attn B' [e][o][whi|wlo|whi]

// recurrence: W_hh split bf16, gate-interleaved cols [c][cg=hd*4+g][k 0..255] (kp-packed)
__device__ uint32_t g_wBhi[(size_t)NCh * G4 * 128];
__device__ uint32_t g_wBlo[(size_t)NCh * G4 * 128];
// h state as bf16 hi/lo [c][m=128][k=hd 0..255]
__device__ __nv_bfloat16 g_hAhi[(size_t)NCh * Bdim * Hdim];
__device__ __nv_bfloat16 g_hAlo[(size_t)NCh * Bdim * Hdim];

// ---------------- helpers ----------------
__device__ __forceinline__ float sigf(float x) { return 1.0f / (1.0f + __expf(-x)); }
__device__ __forceinline__ float tanh_fast(float x) {
    float cx = fminf(fmaxf(x, -15.0f), 15.0f);
    float e = __expf(2.0f * cx);
    return (e - 1.0f) / (e + 1.0f);
}
__device__ __forceinline__ unsigned atom_add_release(unsigned* p, unsigned v) {
    unsigned old;
    asm volatile("atom.release.gpu.global.add.u32 %0, [%1], %2;"
                 : "=r"(old) : "l"(p), "r"(v) : "memory");
    return old;
}
__device__ __forceinline__ unsigned ld_acquire(const unsigned* p) {
    unsigned v;
    asm volatile("ld.acquire.gpu.global.u32 %0, [%1];" : "=r"(v) : "l"(p) : "memory");
    return v;
}
__device__ __forceinline__ void mma16816(float* c, const uint32_t* a, const uint32_t* b) {
    asm volatile(
        "mma.sync.aligned.m16n8k16.row.col.f32.bf16.bf16.f32 "
        "{%0,%1,%2,%3}, {%4,%5,%6,%7}, {%8,%9}, {%0,%1,%2,%3};"
        : "+f"(c[0]), "+f"(c[1]), "+f"(c[2]), "+f"(c[3])
        : "r"(a[0]), "r"(a[1]), "r"(a[2]), "r"(a[3]), "r"(b[0]), "r"(b[1]));
}
__device__ __forceinline__ uint32_t pack_bf2(__nv_bfloat16 a, __nv_bfloat16 b) {
    __nv_bfloat162 p; p.x = a; p.y = b;
    return *(uint32_t*)&p;
}

// ---------------- prep: proj operands (3-term split; B gate-interleaved) ----------------
__global__ __launch_bounds__(256) void prep_proj_kernel(
    const float* __restrict__ x,
    const float* __restrict__ wf, const float* __restrict__ wb)
{
    const int row = blockIdx.x;
    const int tid = threadIdx.x;
    if (row < 16384) {
        const float* src = x + (size_t)row * Vdim;
        __nv_bfloat16* dA = g_pA + (size_t)row * KPP;
        for (int col = tid; col < KPP; col += 256) {
            int s = col / 320, kk = col - s * 320;
            float v = (kk < Vdim) ? src[kk] : 0.0f;
            __nv_bfloat16 hi = __float2bfloat16(v);
            dA[col] = (s < 2) ? hi : __float2bfloat16(v - __bfloat162float(hi));
        }
    } else {
        const int n = row - 16384;                // n = c*1024 + cg
        const int c = n >> 10, e = c >> 1, d = c & 1;
        const int cg = n & 1023;
        const int gt = cg & 3, hd = cg >> 2;
        const float* src = (d ? wb : wf) + ((size_t)e * G4 + gt * 256 + hd) * Vdim;
        __nv_bfloat16* dB = g_pB + (size_t)n * KPP;
        for (int col = tid; col < KPP; col += 256) {
            int s = col / 320, kk = col - s * 320;
            float v = (kk < Vdim) ? src[kk] : 0.0f;
            __nv_bfloat16 hi = __float2bfloat16(v);
            dB[col] = (s == 1) ? __float2bfloat16(v - __bfloat162float(hi)) : hi;
        }
    }
}

// ---------------- prep: W_hh split bf16, gate-interleaved ----------------
__global__ __launch_bounds__(128) void prep_whh_kernel(
    const float* __restrict__ whf, const float* __restrict__ whb)
{
    const int rowid = blockIdx.x;                 // c*1024 + cg
    const int c = rowid >> 10, cg = rowid & 1023;
    const int e = c >> 1, d = c & 1;
    const int gt = cg & 3, hd = cg >> 2;
    const float* src = (d ? whb : whf) + ((size_t)e * G4 + gt * 256 + hd) * Hdim;
    const int kp = threadIdx.x;                   // 0..127
    float v0 = src[2 * kp], v1 = src[2 * kp + 1];
    __nv_bfloat16 h0 = __float2bfloat16(v0);
    __nv_bfloat16 h1 = __float2bfloat16(v1);
    __nv_bfloat16 l0 = __float2bfloat16(v0 - __bfloat162float(h0));
    __nv_bfloat16 l1 = __float2bfloat16(v1 - __bfloat162float(h1));
    g_wBhi[(size_t)rowid * 128 + kp] = pack_bf2(h0, h1);
    g_wBlo[(size_t)rowid * 128 + kp] = pack_bf2(l0, l1);
}

// ---------------- prep: attn B' (whi | wlo | whi) ----------------
__global__ __launch_bounds__(256) void prep_attnB_kernel(const float* __restrict__ attW)
{
    const int r = blockIdx.x;                 // e*512 + o
    const int tid = threadIdx.x;
    const float* src = attW + (size_t)r * H2;
    __nv_bfloat16* dB = g_aB + (size_t)r * KPA;
    for (int col = tid; col < KPA; col += 256) {
        int s = col >> 9, kk = col & 511;
        float v = src[kk];
        __nv_bfloat16 hi = __float2bfloat16(v);
        dB[col] = (s == 1) ? __float2bfloat16(v - __bfloat162float(hi)) : hi;
    }
}

// ---------------- prep: attn A (hi | lo of g_HS) ----------------
__global__ __launch_bounds__(256) void prep_attnA_kernel()
{
    const int r = blockIdx.x;                 // e*16384 + m
    const int tid = threadIdx.x;
    const float* src = g_HS + (size_t)r * H2;
    __nv_bfloat16* dA = g_aA + (size_t)r * 1024;
    for (int col = tid; col < 1024; col += 256) {
        int kk = col & 511;
        float v = src[kk];
        __nv_bfloat16 hi = __float2bfloat16(v);
        dA[col] = (col < 512) ? hi : __float2bfloat16(v - __bfloat162float(hi));
    }
}

// ---------------- proj GEMM (mma.sync bf16) ----------------
__global__ __launch_bounds__(256) void proj_mma_kernel(
    const float* __restrict__ bf, const float* __restrict__ bb)
{
    __shared__ __align__(16) uint32_t As[128][36];
    __shared__ __align__(16) uint32_t Bs[128][36];
    __shared__ float biasS[128];

    const int tid = threadIdx.x;
    const int warp = tid >> 5, lane = tid & 31;
    const int g = lane >> 2, tg = lane & 3;
    const int warp_m = (warp >> 2) * 64;
    const int warp_n = (warp & 3) * 32;

    const int n0 = blockIdx.x * 128;
    const int m0 = blockIdx.y * 128;
    const int b_i = blockIdx.y;
    const int c = n0 >> 10, e = c >> 1, d = c & 1;
    const int g0 = n0 & 1023;

    {
        const float* bias = (d ? bb : bf) + (size_t)e * G4;
        if (tid < 128) {
            int cg = g0 + tid;
            biasS[tid] = bias[(cg & 3) * 256 + (cg >> 2)];
        }
    }

    float acc[4][4][4];
#pragma unroll
    for (int m = 0; m < 4; m++)
#pragma unroll
        for (int n = 0; n < 4; n++)
#pragma unroll
            for (int q = 0; q < 4; q++) acc[m][n][q] = 0.0f;

    const uint4* Ag = (const uint4*)g_pA;
    const uint4* Bg = (const uint4*)g_pB;

    for (int kc = 0; kc < 15; kc++) {
#pragma unroll
        for (int q = 0; q < 4; q++) {
            int idx = tid + q * 256;
            int r = idx >> 3, ju = idx & 7;
            *(uint4*)&As[r][ju * 4] = Ag[(size_t)(m0 + r) * 120 + kc * 8 + ju];
            *(uint4*)&Bs[r][ju * 4] = Bg[(size_t)(n0 + r) * 120 + kc * 8 + ju];
        }
        __syncthreads();
#pragma unroll
        for (int ks = 0; ks < 4; ks++) {
            uint32_t af[4][4], bfr[4][2];
#pragma unroll
            for (int m = 0; m < 4; m++) {
                int r0 = warp_m + m * 16 + g;
                af[m][0] = As[r0][ks * 8 + tg];
                af[m][1] = As[r0 + 8][ks * 8 + tg];
                af[m][2] = As[r0][ks * 8 + tg + 4];
                af[m][3] = As[r0 + 8][ks * 8 + tg + 4];
            }
#pragma unroll
            for (int n = 0; n < 4; n++) {
                int rn = warp_n + n * 8 + g;
                bfr[n][0] = Bs[rn][ks * 8 + tg];
                bfr[n][1] = Bs[rn][ks * 8 + tg + 4];
            }
#pragma unroll
            for (int m = 0; m < 4; m++)
#pragma unroll
                for (int n = 0; n < 4; n++) mma16816(acc[m][n], af[m], bfr[n]);
        }
        __syncthreads();
    }

#pragma unroll
    for (int m = 0; m < 4; m++) {
        int l0 = warp_m + m * 16 + g;
        int l1 = l0 + 8;
        int t0 = d ? (Ldim - 1 - l0) : l0;
        int t1 = d ? (Ldim - 1 - l1) : l1;
        float* base0 = g_PROJ + (((size_t)c * Ldim + t0) * Bdim + b_i) * G4 + g0 + warp_n;
        float* base1 = g_PROJ + (((size_t)c * Ldim + t1) * Bdim + b_i) * G4 + g0 + warp_n;
#pragma unroll
        for (int n = 0; n < 4; n++) {
            int cc = n * 8 + 2 * tg;
            float2 v0 = { acc[m][n][0] + biasS[warp_n + cc],
                          acc[m][n][1] + biasS[warp_n + cc + 1] };
            float2 v1 = { acc[m][n][2] + biasS[warp_n + cc],
                          acc[m][n][3] + biasS[warp_n + cc + 1] };
            *(float2*)(base0 + cc) = v0;
            *(float2*)(base1 + cc) = v1;
        }
    }
}

// ---------------- persistent LSTM recurrence on tensor pipe ----------------
// grid 80 = 10 chains x 8 slices of 32 h-dims (128 gate-interleaved cols).
#define SMEM_LSTM ((128 * 132 * 2 + 128 * 68 * 2) * 4)   // 204,800 B

__global__ __launch_bounds__(256, 1) void lstm_mma_kernel()
{
    extern __shared__ uint32_t smu[];
    uint32_t* Bh = smu;                    // [128][132]
    uint32_t* Bl = Bh + 128 * 132;
    uint32_t* Ah = Bl + 128 * 132;         // [128][68] (k-chunk of 128)
    uint32_t* Al = Ah + 128 * 68;

    const int bid = blockIdx.x;
    const int c = bid >> 3, p = bid & 7;
    const int hd0 = p * 32;
    const int e = c >> 1, d = c & 1;
    const int tid = threadIdx.x;
    const int warp = tid >> 5, lane = tid & 31;
    const int g = lane >> 2, tg = lane & 3;
    const int warp_m = (warp >> 2) * 64;
    const int warp_n = (warp & 3) * 32;
    const bool evenp = (tg & 1) == 0;

    // ---- load W slice (hi+lo) into SMEM once: 128 rows x 32 uint4 each ----
    const uint4* WH = (const uint4*)g_wBhi + ((size_t)c * G4 + p * 128) * 32;
    const uint4* WL = (const uint4*)g_wBlo + ((size_t)c * G4 + p * 128) * 32;
    for (int idx = tid; idx < 4096; idx += 256) {
        int n = idx >> 5, j = idx & 31;
        *(uint4*)&Bh[n * 132 + j * 4] = WH[(size_t)n * 32 + j];
        *(uint4*)&Bl[n * 132 + j * 4] = WL[(size_t)n * 32 + j];
    }

    unsigned bgen = 0;
    if (tid == 0) bgen = ld_acquire(&g_bar_gen[c]);
    __syncthreads();

    float cst[16];
#pragma unroll
    for (int i = 0; i < 16; i++) cst[i] = 0.0f;

    const uint4* AHg = (const uint4*)g_hAhi + (size_t)c * Bdim * 32;
    const uint4* ALg = (const uint4*)g_hAlo + (size_t)c * Bdim * 32;

    for (int t = 0; t < Ldim; t++) {
        float acc[4][4][4];
#pragma unroll
        for (int m = 0; m < 4; m++)
#pragma unroll
            for (int n = 0; n < 4; n++)
#pragma unroll
                for (int q = 0; q < 4; q++) acc[m][n][q] = 0.0f;

        if (t > 0) {
            for (int chunk = 0; chunk < 2; chunk++) {
                __syncthreads();
                for (int idx = tid; idx < 2048; idx += 256) {
                    int m = idx >> 4, j = idx & 15;
                    uint4 vh = __ldcg(&AHg[(size_t)m * 32 + chunk * 16 + j]);
                    uint4 vl = __ldcg(&ALg[(size_t)m * 32 + chunk * 16 + j]);
                    *(uint4*)&Ah[m * 68 + j * 4] = vh;
                    *(uint4*)&Al[m * 68 + j * 4] = vl;
                }
                __syncthreads();
                const int kpB = chunk * 64;
#pragma unroll
                for (int ks = 0; ks < 8; ks++) {
                    uint32_t bh[4][2], bl[4][2];
#pragma unroll
                    for (int n = 0; n < 4; n++) {
                        int rn = warp_n + n * 8 + g;
                        bh[n][0] = Bh[rn * 132 + kpB + ks * 8 + tg];
                        bh[n][1] = Bh[rn * 132 + kpB + ks * 8 + tg + 4];
                        bl[n][0] = Bl[rn * 132 + kpB + ks * 8 + tg];
                        bl[n][1] = Bl[rn * 132 + kpB + ks * 8 + tg + 4];
                    }
#pragma unroll
                    for (int m = 0; m < 4; m++) {
                        int r0 = warp_m + m * 16 + g;
                        uint32_t ah[4], al[4];
                        ah[0] = Ah[r0 * 68 + ks * 8 + tg];
                        ah[1] = Ah[(r0 + 8) * 68 + ks * 8 + tg];
                        ah[2] = Ah[r0 * 68 + ks * 8 + tg + 4];
                        ah[3] = Ah[(r0 + 8) * 68 + ks * 8 + tg + 4];
                        al[0] = Al[r0 * 68 + ks * 8 + tg];
                        al[1] = Al[(r0 + 8) * 68 + ks * 8 + tg];
                        al[2] = Al[r0 * 68 + ks * 8 + tg + 4];
                        al[3] = Al[(r0 + 8) * 68 + ks * 8 + tg + 4];
#pragma unroll
                        for (int n = 0; n < 4; n++) {
                            mma16816(acc[m][n], ah, bh[n]);
                            mma16816(acc[m][n], ah, bl[n]);
                            mma16816(acc[m][n], al, bh[n]);
                        }
                    }
                }
            }
        }

        // ---- pointwise: exchange gate pairs, apply LSTM cell, store h ----
        const int lo_t = d ? (Ldim - 1 - t) : t;
        const float* projb = g_PROJ + (((size_t)c * Ldim + t) * Bdim) * G4;
#pragma unroll
        for (int mt = 0; mt < 4; mt++) {
#pragma unroll
            for (int nt = 0; nt < 4; nt++) {
                float a0 = acc[mt][nt][0], a1 = acc[mt][nt][1];
                float a2 = acc[mt][nt][2], a3 = acc[mt][nt][3];
                float t0 = __shfl_xor_sync(0xFFFFFFFFu, a0, 1);
                float t1 = __shfl_xor_sync(0xFFFFFFFFu, a1, 1);
                float t2 = __shfl_xor_sync(0xFFFFFFFFu, a2, 1);
                float t3 = __shfl_xor_sync(0xFFFFFFFFu, a3, 1);
                int row = warp_m + mt * 16 + g + (evenp ? 0 : 8);
                int hdg = hd0 + ((warp_n + nt * 8) >> 2) + (tg >> 1);
                float4 pj = *(const float4*)(projb + (size_t)row * G4 + hdg * 4);
                float gi = (evenp ? a0 : t2) + pj.x;
                float gf = (evenp ? a1 : t3) + pj.y;
                float gg = (evenp ? t0 : a2) + pj.z;
                float go = (evenp ? t1 : a3) + pj.w;
                int idx = mt * 4 + nt;
                float cn = sigf(gf) * cst[idx] + sigf(gi) * tanh_fast(gg);
                cst[idx] = cn;
                float h = sigf(go) * tanh_fast(cn);
                g_HS[(((size_t)e * Bdim + row) * Ldim + lo_t) * H2 + d * Hdim + hdg] = h;
                __nv_bfloat16 hh = __float2bfloat16(h);
                size_t hidx = ((size_t)c * Bdim + row) * Hdim + hdg;
                g_hAhi[hidx] = hh;
                g_hAlo[hidx] = __float2bfloat16(h - __bfloat162float(hh));
            }
        }

        // ---- chain barrier (release/acquire) ----
        __syncthreads();
        if (tid == 0) {
            unsigned a = atom_add_release(&g_bar_arrive[c], 1u);
            unsigned target = bgen + (unsigned)t + 1u;
            if (a == 7u) {
                g_bar_arrive[c] = 0u;
                atom_add_release(&g_bar_gen[c], 1u);
            } else {
                while ((int)(ld_acquire(&g_bar_gen[c]) - target) < 0)
                    __nanosleep(32);
            }
        }
        __syncthreads();
    }
}

// ---------------- attention logits GEMM (mma.sync bf16) ----------------
__global__ __launch_bounds__(256) void attn_mma_kernel(
    const float* __restrict__ attb, const float* __restrict__ attv)
{
    __shared__ __align__(16) uint32_t As[128][36];
    __shared__ __align__(16) uint32_t Bs[128][36];
    __shared__ float red[128][17];

    const int tid = threadIdx.x;
    const int warp = tid >> 5, lane = tid & 31;
    const int g = lane >> 2, tg = lane & 3;
    const int warp_m = (warp >> 2) * 64;
    const int warp_n = (warp & 3) * 32;

    const int m0 = blockIdx.x * 128;
    const int e = blockIdx.y;

    const uint4* Ag = (const uint4*)g_aA;
    const uint4* Bg = (const uint4*)g_aB;
    const float* abp = attb + (size_t)e * H2;
    const float* avp = attv + (size_t)e * H2;

    float part[4][2];
#pragma unroll
    for (int m = 0; m < 4; m++) { part[m][0] = 0.0f; part[m][1] = 0.0f; }

    for (int nc = 0; nc < 4; nc++) {
        const int n0 = nc * 128;
        float acc[4][4][4];
#pragma unroll
        for (int m = 0; m < 4; m++)
#pragma unroll
            for (int n = 0; n < 4; n++)
#pragma unroll
                for (int q = 0; q < 4; q++) acc[m][n][q] = 0.0f;

        for (int kc = 0; kc < 24; kc++) {
            const int pp = kc >> 3, within = kc & 7;
            const int au4 = (pp == 2 ? 64 : 0) + within * 8;
            const int bu4 = kc * 8;
#pragma unroll
            for (int q = 0; q < 4; q++) {
                int idx = tid + q * 256;
                int r = idx >> 3, ju = idx & 7;
                *(uint4*)&As[r][ju * 4] =
                    Ag[((size_t)e * 16384 + m0 + r) * 128 + au4 + ju];
                *(uint4*)&Bs[r][ju * 4] =
                    Bg[((size_t)e * H2 + n0 + r) * 192 + bu4 + ju];
            }
            __syncthreads();
#pragma unroll
            for (int ks = 0; ks < 4; ks++) {
                uint32_t af[4][4], bfr[4][2];
#pragma unroll
                for (int m = 0; m < 4; m++) {
                    int r0 = warp_m + m * 16 + g;
                    af[m][0] = As[r0][ks * 8 + tg];
                    af[m][1] = As[r0 + 8][ks * 8 + tg];
                    af[m][2] = As[r0][ks * 8 + tg + 4];
                    af[m][3] = As[r0 + 8][ks * 8 + tg + 4];
                }
#pragma unroll
                for (int n = 0; n < 4; n++) {
                    int rn = warp_n + n * 8 + g;
                    bfr[n][0] = Bs[rn][ks * 8 + tg];
                    bfr[n][1] = Bs[rn][ks * 8 + tg + 4];
                }
#pragma unroll
                for (int m = 0; m < 4; m++)
#pragma unroll
                    for (int n = 0; n < 4; n++) mma16816(acc[m][n], af[m], bfr[n]);
            }
            __syncthreads();
        }

#pragma unroll
        for (int n = 0; n < 4; n++) {
            int o = n0 + warp_n + n * 8 + 2 * tg;
            float ab0 = abp[o], ab1 = abp[o + 1];
            float av0 = avp[o], av1 = avp[o + 1];
#pragma unroll
            for (int m = 0; m < 4; m++) {
                part[m][0] += tanh_fast(acc[m][n][0] + ab0) * av0
                            + tanh_fast(acc[m][n][1] + ab1) * av1;
                part[m][1] += tanh_fast(acc[m][n][2] + ab0) * av0
                            + tanh_fast(acc[m][n][3] + ab1) * av1;
            }
        }
    }

#pragma unroll
    for (int m = 0; m < 4; m++) {
        int r0 = warp_m + m * 16 + g;
        red[r0][(warp & 3) * 4 + tg] = part[m][0];
        red[r0 + 8][(warp & 3) * 4 + tg] = part[m][1];
    }
    __syncthreads();
    if (tid < 128) {
        float s = 0.0f;
#pragma unroll
        for (int q = 0; q < 16; q++) s += red[tid][q];
        g_s[(size_t)e * Bdim * Ldim + m0 + tid] = s;
    }
}

// ---------------- softmax over L + weighted pooling ----------------
__global__ __launch_bounds__(128) void softmax_pool_kernel()
{
    const int e = blockIdx.y, b = blockIdx.x;
    __shared__ float wts[Ldim];
    __shared__ float red[128];
    const int tid = threadIdx.x;

    float v = g_s[((size_t)e * Bdim + b) * Ldim + tid];
    red[tid] = v; __syncthreads();
    for (int st = 64; st > 0; st >>= 1) {
        if (tid < st) red[tid] = fmaxf(red[tid], red[tid + st]);
        __syncthreads();
    }
    float mx = red[0]; __syncthreads();
    float ev = expf(v - mx);
    red[tid] = ev; __syncthreads();
    for (int st = 64; st > 0; st >>= 1) {
        if (tid < st) red[tid] += red[tid + st];
        __syncthreads();
    }
    float inv = 1.0f / red[0];
    wts[tid] = ev * inv;
    __syncthreads();

    const float* hrow = g_HS + ((size_t)e * Bdim + b) * Ldim * H2;
    float accv[4] = {0.f, 0.f, 0.f, 0.f};
    for (int l = 0; l < Ldim; l++) {
        float a = wts[l];
        const float* hp = hrow + (size_t)l * H2;
#pragma unroll
        for (int j = 0; j < 4; j++) accv[j] += a * hp[tid + j * 128];
    }
    float* op = g_OUT + ((size_t)e * Bdim + b) * H2;
#pragma unroll
    for (int j = 0; j < 4; j++) op[tid + j * 128] = accv[j];
}

// ---------------- output copy + final FC ----------------
__global__ void copy_out_kernel(float* __restrict__ out)
{
    int i = blockIdx.x * blockDim.x + threadIdx.x;
    if (i < NEx * Bdim * H2) out[256 + i] = g_OUT[i];
}

__global__ __launch_bounds__(128) void final_kernel(
    const int* __restrict__ z, const float* __restrict__ fcW,
    const float* __restrict__ fcb, float* __restrict__ out)
{
    const int b = blockIdx.x;
    const int tid = threadIdx.x;
    const int zi = z[b];
    const float* sel = g_OUT + ((size_t)(1 + zi) * Bdim + b) * H2;
    const float* gen = g_OUT + (size_t)b * H2;
    __shared__ float red0[128], red1[128];
    float a0 = 0.f, a1 = 0.f;
    for (int dd = tid; dd < 1024; dd += 128) {
        float cv = (dd < 512) ? sel[dd] : gen[dd - 512];
        a0 += cv * fcW[dd];
        a1 += cv * fcW[1024 + dd];
    }
    red0[tid] = a0; red1[tid] = a1; __syncthreads();
    for (int st = 64; st > 0; st >>= 1) {
        if (tid < st) { red0[tid] += red0[tid + st]; red1[tid] += red1[tid + st]; }
        __syncthreads();
    }
    if (tid == 0) {
        out[b * 2 + 0] = red0[0] + fcb[0];
        out[b * 2 + 1] = red1[0] + fcb[1];
    }
}

// ---------------- launch ----------------
extern "C" void kernel_launch(void* const* d_in, const int* in_sizes, int n_in,
                              void* d_out, int out_size)
{
    (void)in_sizes; (void)n_in; (void)out_size;
    const float* x     = (const float*)d_in[0];
    const int*   z     = (const int*)  d_in[1];
    const float* wih_f = (const float*)d_in[2];
    const float* whh_f = (const float*)d_in[3];
    const float* b_f   = (const float*)d_in[4];
    const float* wih_b = (const float*)d_in[5];
    const float* whh_b = (const float*)d_in[6];
    const float* b_b   = (const float*)d_in[7];
    const float* attW  = (const float*)d_in[8];
    const float* attb  = (const float*)d_in[9];
    const float* attv  = (const float*)d_in[10];
    const float* fcW   = (const float*)d_in[11];
    const float* fcb   = (const float*)d_in[12];
    float* out = (float*)d_out;

    cudaFuncSetAttribute(lstm_mma_kernel,
                         cudaFuncAttributeMaxDynamicSharedMemorySize, SMEM_LSTM);

    prep_proj_kernel<<<16384 + 10240, 256>>>(x, wih_f, wih_b);
    prep_whh_kernel<<<NCh * G4, 128>>>(whh_f, whh_b);
    prep_attnB_kernel<<<NEx * H2, 256>>>(attW);
    proj_mma_kernel<<<dim3(80, 128), 256>>>(b_f, b_b);
    lstm_mma_kernel<<<80, 256, SMEM_LSTM>>>();
    prep_attnA_kernel<<<NEx * 16384, 256>>>();
    attn_mma_kernel<<<dim3(128, 5), 256>>>(attb, attv);
    softmax_pool_kernel<<<dim3(128, 5), 128>>>();
    copy_out_kernel<<<(NEx * Bdim * H2 + 255) / 256, 256>>>(out);
    final_kernel<<<128, 128>>>(z, fcW, fcb, out);
}

// round 10
// speedup vs baseline: 3.3533x; 1.1404x over previous
#include <cuda_runtime.h>
#include <cuda_bf16.h>
#include <cstdint>
#include <stdint.h>
#include <math.h>

#define Ldim 128
#define Bdim 128
#define Vdim 300
#define Hdim 256
#define NEx  5
#define NCh  10      // 5 experts x 2 directions
#define G4   1024    // 4*H
#define H2   512     // 2*H
#define KPP  960     // proj K: 3 x 320 (hi, hi, lo sections)
#define KPA  1536    // attn K: 3 x 512

// ---------------- device scratch (no allocations allowed) ----------------
// g_PROJ gate-interleaved: [c][t][b][cg], cg = hd*4 + gate.
__device__ float g_PROJ[(size_t)NCh * Ldim * Bdim * G4];
__device__ float g_HS[(size_t)NEx * Bdim * Ldim * H2];     // [e][b][l][2H]
__device__ float g_s[(size_t)NEx * Bdim * Ldim];           // attention logits
__device__ float g_OUT[(size_t)NEx * Bdim * H2];           // pooled outputs

// bf16 split GEMM operands
__device__ __nv_bfloat16 g_pA[(size_t)16384 * KPP];        // proj A' [m][960]
__device__ __nv_bfloat16 g_pB[(size_t)10240 * KPP];        // proj B' [cg-ordered][960]
__device__ __nv_bfloat16 g_aA[(size_t)NEx * 16384 * 1024]; // attn A [e][m][hi512|lo512]
__device__ __nv_bfloat16 g_aB[(size_t)NEx * H2 * KPA];     // attn B' [e][o][whi|wlo|whi]

// recurrence W_hh as per-lane MMA fragments:
// g_wT[c][w][kt][nt][lane] = uint4 {bh0, bh1, bl0, bl1}  (10 MB total)
__device__ uint4 g_wT[(size_t)NCh * 8 * 16 * 16 * 32];

// ---------------- helpers ----------------
__device__ __forceinline__ float sigf(float x) { return 1.0f / (1.0f + __expf(-x)); }
__device__ __forceinline__ float tanh_fast(float x) {
    float cx = fminf(fmaxf(x, -15.0f), 15.0f);
    float e = __expf(2.0f * cx);
    return (e - 1.0f) / (e + 1.0f);
}
__device__ __forceinline__ void mma16816(float* c, const uint32_t* a, const uint32_t* b) {
    asm volatile(
        "mma.sync.aligned.m16n8k16.row.col.f32.bf16.bf16.f32 "
        "{%0,%1,%2,%3}, {%4,%5,%6,%7}, {%8,%9}, {%0,%1,%2,%3};"
        : "+f"(c[0]), "+f"(c[1]), "+f"(c[2]), "+f"(c[3])
        : "r"(a[0]), "r"(a[1]), "r"(a[2]), "r"(a[3]), "r"(b[0]), "r"(b[1]));
}
__device__ __forceinline__ uint32_t pack_bf2(__nv_bfloat16 a, __nv_bfloat16 b) {
    __nv_bfloat162 p; p.x = a; p.y = b;
    return *(uint32_t*)&p;
}

// ---------------- prep: proj operands (3-term split; B gate-interleaved) ----------------
__global__ __launch_bounds__(256) void prep_proj_kernel(
    const float* __restrict__ x,
    const float* __restrict__ wf, const float* __restrict__ wb)
{
    const int row = blockIdx.x;
    const int tid = threadIdx.x;
    if (row < 16384) {
        const float* src = x + (size_t)row * Vdim;
        __nv_bfloat16* dA = g_pA + (size_t)row * KPP;
        for (int col = tid; col < KPP; col += 256) {
            int s = col / 320, kk = col - s * 320;
            float v = (kk < Vdim) ? src[kk] : 0.0f;
            __nv_bfloat16 hi = __float2bfloat16(v);
            dA[col] = (s < 2) ? hi : __float2bfloat16(v - __bfloat162float(hi));
        }
    } else {
        const int n = row - 16384;                // n = c*1024 + cg
        const int c = n >> 10, e = c >> 1, d = c & 1;
        const int cg = n & 1023;
        const int gt = cg & 3, hd = cg >> 2;
        const float* src = (d ? wb : wf) + ((size_t)e * G4 + gt * 256 + hd) * Vdim;
        __nv_bfloat16* dB = g_pB + (size_t)n * KPP;
        for (int col = tid; col < KPP; col += 256) {
            int s = col / 320, kk = col - s * 320;
            float v = (kk < Vdim) ? src[kk] : 0.0f;
            __nv_bfloat16 hi = __float2bfloat16(v);
            dB[col] = (s == 1) ? __float2bfloat16(v - __bfloat162float(hi)) : hi;
        }
    }
}

// ---------------- prep: W_hh fragment layout ----------------
__global__ __launch_bounds__(256) void prep_wT_kernel(
    const float* __restrict__ whf, const float* __restrict__ whb)
{
    const int idx = blockIdx.x * 256 + threadIdx.x;   // 655360 total
    const int lane = idx & 31;
    const int nt = (idx >> 5) & 15;
    const int kt = (idx >> 9) & 15;
    const int w = (idx >> 13) & 7;
    const int c = idx >> 16;
    const int e = c >> 1, d = c & 1;
    const int cg = w * 128 + nt * 8 + (lane >> 2);
    const int gate = cg & 3, hd = cg >> 2;
    const float* src = (d ? whb : whf) + ((size_t)e * G4 + gate * 256 + hd) * Hdim;
    const int k0 = kt * 16 + (lane & 3) * 2;
    float v00 = src[k0],     v01 = src[k0 + 1];
    float v10 = src[k0 + 8], v11 = src[k0 + 9];
    __nv_bfloat16 h00 = __float2bfloat16(v00), h01 = __float2bfloat16(v01);
    __nv_bfloat16 h10 = __float2bfloat16(v10), h11 = __float2bfloat16(v11);
    uint4 o;
    o.x = pack_bf2(h00, h01);
    o.y = pack_bf2(h10, h11);
    o.z = pack_bf2(__float2bfloat16(v00 - __bfloat162float(h00)),
                   __float2bfloat16(v01 - __bfloat162float(h01)));
    o.w = pack_bf2(__float2bfloat16(v10 - __bfloat162float(h10)),
                   __float2bfloat16(v11 - __bfloat162float(h11)));
    g_wT[idx] = o;
}

// ---------------- prep: attn B' (whi | wlo | whi) ----------------
__global__ __launch_bounds__(256) void prep_attnB_kernel(const float* __restrict__ attW)
{
    const int r = blockIdx.x;                 // e*512 + o
    const int tid = threadIdx.x;
    const float* src = attW + (size_t)r * H2;
    __nv_bfloat16* dB = g_aB + (size_t)r * KPA;
    for (int col = tid; col < KPA; col += 256) {
        int s = col >> 9, kk = col & 511;
        float v = src[kk];
        __nv_bfloat16 hi = __float2bfloat16(v);
        dB[col] = (s == 1) ? __float2bfloat16(v - __bfloat162float(hi)) : hi;
    }
}

// ---------------- prep: attn A (hi | lo of g_HS) ----------------
__global__ __launch_bounds__(256) void prep_attnA_kernel()
{
    const int r = blockIdx.x;                 // e*16384 + m
    const int tid = threadIdx.x;
    const float* src = g_HS + (size_t)r * H2;
    __nv_bfloat16* dA = g_aA + (size_t)r * 1024;
    for (int col = tid; col < 1024; col += 256) {
        int kk = col & 511;
        float v = src[kk];
        __nv_bfloat16 hi = __float2bfloat16(v);
        dA[col] = (col < 512) ? hi : __float2bfloat16(v - __bfloat162float(hi));
    }
}

// ---------------- proj GEMM (mma.sync bf16) ----------------
__global__ __launch_bounds__(256) void proj_mma_kernel(
    const float* __restrict__ bf, const float* __restrict__ bb)
{
    __shared__ __align__(16) uint32_t As[128][36];
    __shared__ __align__(16) uint32_t Bs[128][36];
    __shared__ float biasS[128];

    const int tid = threadIdx.x;
    const int warp = tid >> 5, lane = tid & 31;
    const int g = lane >> 2, tg = lane & 3;
    const int warp_m = (warp >> 2) * 64;
    const int warp_n = (warp & 3) * 32;

    const int n0 = blockIdx.x * 128;
    const int m0 = blockIdx.y * 128;
    const int b_i = blockIdx.y;
    const int c = n0 >> 10, e = c >> 1, d = c & 1;
    const int g0 = n0 & 1023;

    {
        const float* bias = (d ? bb : bf) + (size_t)e * G4;
        if (tid < 128) {
            int cg = g0 + tid;
            biasS[tid] = bias[(cg & 3) * 256 + (cg >> 2)];
        }
    }

    float acc[4][4][4];
#pragma unroll
    for (int m = 0; m < 4; m++)
#pragma unroll
        for (int n = 0; n < 4; n++)
#pragma unroll
            for (int q = 0; q < 4; q++) acc[m][n][q] = 0.0f;

    const uint4* Ag = (const uint4*)g_pA;
    const uint4* Bg = (const uint4*)g_pB;

    for (int kc = 0; kc < 15; kc++) {
#pragma unroll
        for (int q = 0; q < 4; q++) {
            int idx = tid + q * 256;
            int r = idx >> 3, ju = idx & 7;
            *(uint4*)&As[r][ju * 4] = Ag[(size_t)(m0 + r) * 120 + kc * 8 + ju];
            *(uint4*)&Bs[r][ju * 4] = Bg[(size_t)(n0 + r) * 120 + kc * 8 + ju];
        }
        __syncthreads();
#pragma unroll
        for (int ks = 0; ks < 4; ks++) {
            uint32_t af[4][4], bfr[4][2];
#pragma unroll
            for (int m = 0; m < 4; m++) {
                int r0 = warp_m + m * 16 + g;
                af[m][0] = As[r0][ks * 8 + tg];
                af[m][1] = As[r0 + 8][ks * 8 + tg];
                af[m][2] = As[r0][ks * 8 + tg + 4];
                af[m][3] = As[r0 + 8][ks * 8 + tg + 4];
            }
#pragma unroll
            for (int n = 0; n < 4; n++) {
                int rn = warp_n + n * 8 + g;
                bfr[n][0] = Bs[rn][ks * 8 + tg];
                bfr[n][1] = Bs[rn][ks * 8 + tg + 4];
            }
#pragma unroll
            for (int m = 0; m < 4; m++)
#pragma unroll
                for (int n = 0; n < 4; n++) mma16816(acc[m][n], af[m], bfr[n]);
        }
        __syncthreads();
    }

#pragma unroll
    for (int m = 0; m < 4; m++) {
        int l0 = warp_m + m * 16 + g;
        int l1 = l0 + 8;
        int t0 = d ? (Ldim - 1 - l0) : l0;
        int t1 = d ? (Ldim - 1 - l1) : l1;
        float* base0 = g_PROJ + (((size_t)c * Ldim + t0) * Bdim + b_i) * G4 + g0 + warp_n;
        float* base1 = g_PROJ + (((size_t)c * Ldim + t1) * Bdim + b_i) * G4 + g0 + warp_n;
#pragma unroll
        for (int n = 0; n < 4; n++) {
            int cc = n * 8 + 2 * tg;
            float2 v0 = { acc[m][n][0] + biasS[warp_n + cc],
                          acc[m][n][1] + biasS[warp_n + cc + 1] };
            float2 v1 = { acc[m][n][2] + biasS[warp_n + cc],
                          acc[m][n][3] + biasS[warp_n + cc + 1] };
            *(float2*)(base0 + cc) = v0;
            *(float2*)(base1 + cc) = v1;
        }
    }
}

// ---------------- LSTM recurrence: batch-partitioned, barrier-free ----------------
// grid 80 = 10 chains x 8 batch-slices of 16 rows. Each CTA computes ALL 1024
// gates for its 16 batch rows -> h is CTA-private (SMEM), no inter-CTA sync.
// W_hh streamed from L2 each step in fragment layout (one LDG.128 per lane per tile).
__global__ __launch_bounds__(256, 1) void lstm_batch_kernel()
{
    __shared__ uint32_t Hhi[16][132];
    __shared__ uint32_t Hlo[16][132];

    const int bid = blockIdx.x;
    const int c = bid >> 3, s = bid & 7;
    const int b0 = s * 16;
    const int e = c >> 1, d = c & 1;
    const int tid = threadIdx.x;
    const int warp = tid >> 5, lane = tid & 31;
    const int g = lane >> 2, tg = lane & 3;
    const bool evenp = (tg & 1) == 0;

    const uint4* Wbase = g_wT + ((size_t)c * 8 + warp) * 256 * 32;

    float cst[16];
#pragma unroll
    for (int i = 0; i < 16; i++) cst[i] = 0.0f;

    for (int t = 0; t < Ldim; t++) {
        float acc[16][4];
#pragma unroll
        for (int nt = 0; nt < 16; nt++)
#pragma unroll
            for (int q = 0; q < 4; q++) acc[nt][q] = 0.0f;

        if (t > 0) {
#pragma unroll 2
            for (int kt = 0; kt < 16; kt++) {
                uint32_t ah[4], al[4];
                ah[0] = Hhi[g][kt * 8 + tg];
                ah[1] = Hhi[g + 8][kt * 8 + tg];
                ah[2] = Hhi[g][kt * 8 + tg + 4];
                ah[3] = Hhi[g + 8][kt * 8 + tg + 4];
                al[0] = Hlo[g][kt * 8 + tg];
                al[1] = Hlo[g + 8][kt * 8 + tg];
                al[2] = Hlo[g][kt * 8 + tg + 4];
                al[3] = Hlo[g + 8][kt * 8 + tg + 4];
                const uint4* wrow = Wbase + kt * 16 * 32 + lane;
#pragma unroll
                for (int nt = 0; nt < 16; nt++) {
                    uint4 wv = __ldcg(wrow + nt * 32);
                    uint32_t bh[2] = { wv.x, wv.y };
                    uint32_t bl[2] = { wv.z, wv.w };
                    mma16816(acc[nt], ah, bh);
                    mma16816(acc[nt], ah, bl);
                    mma16816(acc[nt], al, bh);
                }
            }
        }
        __syncthreads();   // all A-frag reads of step t done before h overwrite

        // ---- pointwise: gate exchange (xor 1), LSTM cell, h -> SMEM + g_HS ----
        const int lo_t = d ? (Ldim - 1 - t) : t;
        const float* projb = g_PROJ + (((size_t)c * Ldim + t) * Bdim + b0) * G4;
        const int row = g + (evenp ? 0 : 8);
#pragma unroll
        for (int nt = 0; nt < 16; nt++) {
            float a0 = acc[nt][0], a1 = acc[nt][1];
            float a2 = acc[nt][2], a3 = acc[nt][3];
            float t0 = __shfl_xor_sync(0xFFFFFFFFu, a0, 1);
            float t1 = __shfl_xor_sync(0xFFFFFFFFu, a1, 1);
            float t2 = __shfl_xor_sync(0xFFFFFFFFu, a2, 1);
            float t3 = __shfl_xor_sync(0xFFFFFFFFu, a3, 1);
            int hd = warp * 32 + nt * 2 + (tg >> 1);
            float4 pj = *(const float4*)(projb + (size_t)row * G4 + hd * 4);
            float gi = (evenp ? a0 : t2) + pj.x;
            float gf = (evenp ? a1 : t3) + pj.y;
            float gg = (evenp ? t0 : a2) + pj.z;
            float go = (evenp ? t1 : a3) + pj.w;
            float cn = sigf(gf) * cst[nt] + sigf(gi) * tanh_fast(gg);
            cst[nt] = cn;
            float h = sigf(go) * tanh_fast(cn);
            g_HS[(((size_t)e * Bdim + (b0 + row)) * Ldim + lo_t) * H2 + d * Hdim + hd] = h;
            // pack (even hd, odd hd) pair: partner = lane xor 2 (same row)
            float hB = __shfl_xor_sync(0xFFFFFFFFu, h, 2);
            if ((tg >> 1) == 0) {
                __nv_bfloat16 hhA = __float2bfloat16(h);
                __nv_bfloat16 hhB = __float2bfloat16(hB);
                Hhi[row][warp * 16 + nt] = pack_bf2(hhA, hhB);
                Hlo[row][warp * 16 + nt] = pack_bf2(
                    __float2bfloat16(h - __bfloat162float(hhA)),
                    __float2bfloat16(hB - __bfloat162float(hhB)));
            }
        }
        __syncthreads();   // h writes visible before next step's A-frag reads
    }
}

// ---------------- attention logits GEMM (mma.sync bf16) ----------------
__global__ __launch_bounds__(256) void attn_mma_kernel(
    const float* __restrict__ attb, const float* __restrict__ attv)
{
    __shared__ __align__(16) uint32_t As[128][36];
    __shared__ __align__(16) uint32_t Bs[128][36];
    __shared__ float red[128][17];

    const int tid = threadIdx.x;
    const int warp = tid >> 5, lane = tid & 31;
    const int g = lane >> 2, tg = lane & 3;
    const int warp_m = (warp >> 2) * 64;
    const int warp_n = (warp & 3) * 32;

    const int m0 = blockIdx.x * 128;
    const int e = blockIdx.y;

    const uint4* Ag = (const uint4*)g_aA;
    const uint4* Bg = (const uint4*)g_aB;
    const float* abp = attb + (size_t)e * H2;
    const float* avp = attv + (size_t)e * H2;

    float part[4][2];
#pragma unroll
    for (int m = 0; m < 4; m++) { part[m][0] = 0.0f; part[m][1] = 0.0f; }

    for (int nc = 0; nc < 4; nc++) {
        const int n0 = nc * 128;
        float acc[4][4][4];
#pragma unroll
        for (int m = 0; m < 4; m++)
#pragma unroll
            for (int n = 0; n < 4; n++)
#pragma unroll
                for (int q = 0; q < 4; q++) acc[m][n][q] = 0.0f;

        for (int kc = 0; kc < 24; kc++) {
            const int pp = kc >> 3, within = kc & 7;
            const int au4 = (pp == 2 ? 64 : 0) + within * 8;
            const int bu4 = kc * 8;
#pragma unroll
            for (int q = 0; q < 4; q++) {
                int idx = tid + q * 256;
                int r = idx >> 3, ju = idx & 7;
                *(uint4*)&As[r][ju * 4] =
                    Ag[((size_t)e * 16384 + m0 + r) * 128 + au4 + ju];
                *(uint4*)&Bs[r][ju * 4] =
                    Bg[((size_t)e * H2 + n0 + r) * 192 + bu4 + ju];
            }
            __syncthreads();
#pragma unroll
            for (int ks = 0; ks < 4; ks++) {
                uint32_t af[4][4], bfr[4][2];
#pragma unroll
                for (int m = 0; m < 4; m++) {
                    int r0 = warp_m + m * 16 + g;
                    af[m][0] = As[r0][ks * 8 + tg];
                    af[m][1] = As[r0 + 8][ks * 8 + tg];
                    af[m][2] = As[r0][ks * 8 + tg + 4];
                    af[m][3] = As[r0 + 8][ks * 8 + tg + 4];
                }
#pragma unroll
                for (int n = 0; n < 4; n++) {
                    int rn = warp_n + n * 8 + g;
                    bfr[n][0] = Bs[rn][ks * 8 + tg];
                    bfr[n][1] = Bs[rn][ks * 8 + tg + 4];
                }
#pragma unroll
                for (int m = 0; m < 4; m++)
#pragma unroll
                    for (int n = 0; n < 4; n++) mma16816(acc[m][n], af[m], bfr[n]);
            }
            __syncthreads();
        }

#pragma unroll
        for (int n = 0; n < 4; n++) {
            int o = n0 + warp_n + n * 8 + 2 * tg;
            float ab0 = abp[o], ab1 = abp[o + 1];
            float av0 = avp[o], av1 = avp[o + 1];
#pragma unroll
            for (int m = 0; m < 4; m++) {
                part[m][0] += tanh_fast(acc[m][n][0] + ab0) * av0
                            + tanh_fast(acc[m][n][1] + ab1) * av1;
                part[m][1] += tanh_fast(acc[m][n][2] + ab0) * av0
                            + tanh_fast(acc[m][n][3] + ab1) * av1;
            }
        }
    }

#pragma unroll
    for (int m = 0; m < 4; m++) {
        int r0 = warp_m + m * 16 + g;
        red[r0][(warp & 3) * 4 + tg] = part[m][0];
        red[r0 + 8][(warp & 3) * 4 + tg] = part[m][1];
    }
    __syncthreads();
    if (tid < 128) {
        float ss = 0.0f;
#pragma unroll
        for (int q = 0; q < 16; q++) ss += red[tid][q];
        g_s[(size_t)e * Bdim * Ldim + m0 + tid] = ss;
    }
}

// ---------------- softmax over L + weighted pooling ----------------
__global__ __launch_bounds__(128) void softmax_pool_kernel()
{
    const int e = blockIdx.y, b = blockIdx.x;
    __shared__ float wts[Ldim];
    __shared__ float red[128];
    const int tid = threadIdx.x;

    float v = g_s[((size_t)e * Bdim + b) * Ldim + tid];
    red[tid] = v; __syncthreads();
    for (int st = 64; st > 0; st >>= 1) {
        if (tid < st) red[tid] = fmaxf(red[tid], red[tid + st]);
        __syncthreads();
    }
    float mx = red[0]; __syncthreads();
    float ev = expf(v - mx);
    red[tid] = ev; __syncthreads();
    for (int st = 64; st > 0; st >>= 1) {
        if (tid < st) red[tid] += red[tid + st];
        __syncthreads();
    }
    float inv = 1.0f / red[0];
    wts[tid] = ev * inv;
    __syncthreads();

    const float* hrow = g_HS + ((size_t)e * Bdim + b) * Ldim * H2;
    float accv[4] = {0.f, 0.f, 0.f, 0.f};
    for (int l = 0; l < Ldim; l++) {
        float a = wts[l];
        const float* hp = hrow + (size_t)l * H2;
#pragma unroll
        for (int j = 0; j < 4; j++) accv[j] += a * hp[tid + j * 128];
    }
    float* op = g_OUT + ((size_t)e * Bdim + b) * H2;
#pragma unroll
    for (int j = 0; j < 4; j++) op[tid + j * 128] = accv[j];
}

// ---------------- output copy + final FC ----------------
__global__ void copy_out_kernel(float* __restrict__ out)
{
    int i = blockIdx.x * blockDim.x + threadIdx.x;
    if (i < NEx * Bdim * H2) out[256 + i] = g_OUT[i];
}

__global__ __launch_bounds__(128) void final_kernel(
    const int* __restrict__ z, const float* __restrict__ fcW,
    const float* __restrict__ fcb, float* __restrict__ out)
{
    const int b = blockIdx.x;
    const int tid = threadIdx.x;
    const int zi = z[b];
    const float* sel = g_OUT + ((size_t)(1 + zi) * Bdim + b) * H2;
    const float* gen = g_OUT + (size_t)b * H2;
    __shared__ float red0[128], red1[128];
    float a0 = 0.f, a1 = 0.f;
    for (int dd = tid; dd < 1024; dd += 128) {
        float cv = (dd < 512) ? sel[dd] : gen[dd - 512];
        a0 += cv * fcW[dd];
        a1 += cv * fcW[1024 + dd];
    }
    red0[tid] = a0; red1[tid] = a1; __syncthreads();
    for (int st = 64; st > 0; st >>= 1) {
        if (tid < st) { red0[tid] += red0[tid + st]; red1[tid] += red1[tid + st]; }
        __syncthreads();
    }
    if (tid == 0) {
        out[b * 2 + 0] = red0[0] + fcb[0];
        out[b * 2 + 1] = red1[0] + fcb[1];
    }
}

// ---------------- launch ----------------
extern "C" void kernel_launch(void* const* d_in, const int* in_sizes, int n_in,
                              void* d_out, int out_size)
{
    (void)in_sizes; (void)n_in; (void)out_size;
    const float* x     = (const float*)d_in[0];
    const int*   z     = (const int*)  d_in[1];
    const float* wih_f = (const float*)d_in[2];
    const float* whh_f = (const float*)d_in[3];
    const float* b_f   = (const float*)d_in[4];
    const float* wih_b = (const float*)d_in[5];
    const float* whh_b = (const float*)d_in[6];
    const float* b_b   = (const float*)d_in[7];
    const float* attW  = (const float*)d_in[8];
    const float* attb  = (const float*)d_in[9];
    const float* attv  = (const float*)d_in[10];
    const float* fcW   = (const float*)d_in[11];
    const float* fcb   = (const float*)d_in[12];
    float* out = (float*)d_out;

    prep_proj_kernel<<<16384 + 10240, 256>>>(x, wih_f, wih_b);
    prep_wT_kernel<<<2560, 256>>>(whh_f, whh_b);
    prep_attnB_kernel<<<NEx * H2, 256>>>(attW);
    proj_mma_kernel<<<dim3(80, 128), 256>>>(b_f, b_b);
    lstm_batch_kernel<<<80, 256>>>();
    prep_attnA_kernel<<<NEx * 16384, 256>>>();
    attn_mma_kernel<<<dim3(128, 5), 256>>>(attb, attv);
    softmax_pool_kernel<<<dim3(128, 5), 128>>>();
    copy_out_kernel<<<(NEx * Bdim * H2 + 255) / 256, 256>>>(out);
    final_kernel<<<128, 128>>>(z, fcW, fcb, out);
}